// round 1
// baseline (speedup 1.0000x reference)
#include <cuda_runtime.h>
#include <math.h>

#define L_SEQ 4096
#define D_MODEL 2048
#define NH 8
#define NKVH 2
#define HD 256
#define WINDOW 512

// Scratch (no cudaMalloc allowed): q/k/v post-projection, attention output.
__device__ float g_q[L_SEQ * NH * HD];     // (L, H, HD) == (L, H*HD)
__device__ float g_k[L_SEQ * NKVH * HD];
__device__ float g_v[L_SEQ * NKVH * HD];
__device__ float g_att[L_SEQ * NH * HD];

// ---------------------------------------------------------------------------
// Tiled fp32 GEMM: C[M,N] = A[M,K] @ B[K,N], all row-major.
// BM=BN=64, BK=16, 256 threads, 4x4 per thread. Dims are all divisible.
// ---------------------------------------------------------------------------
__global__ void gemm_kernel(const float* __restrict__ A,
                            const float* __restrict__ B,
                            float* __restrict__ C,
                            int M, int N, int K) {
    constexpr int BM = 64, BN = 64, BK = 16, TM = 4, TN = 4;
    __shared__ float As[BK][BM + 1];
    __shared__ float Bs[BK][BN];

    const int bm = blockIdx.y * BM;
    const int bn = blockIdx.x * BN;
    const int tid = threadIdx.x;
    const int tm = (tid / 16) * TM;
    const int tn = (tid % 16) * TN;

    float acc[TM][TN];
#pragma unroll
    for (int i = 0; i < TM; i++)
#pragma unroll
        for (int j = 0; j < TN; j++) acc[i][j] = 0.f;

    for (int k0 = 0; k0 < K; k0 += BK) {
        // load A tile (64x16)
#pragma unroll
        for (int i = tid; i < BM * BK; i += 256) {
            int m = i / BK, kk = i % BK;
            As[kk][m] = A[(size_t)(bm + m) * K + k0 + kk];
        }
        // load B tile (16x64)
#pragma unroll
        for (int i = tid; i < BK * BN; i += 256) {
            int kk = i / BN, n = i % BN;
            Bs[kk][n] = B[(size_t)(k0 + kk) * N + bn + n];
        }
        __syncthreads();
#pragma unroll
        for (int kk = 0; kk < BK; kk++) {
            float a[TM], b[TN];
#pragma unroll
            for (int i = 0; i < TM; i++) a[i] = As[kk][tm + i];
#pragma unroll
            for (int j = 0; j < TN; j++) b[j] = Bs[kk][tn + j];
#pragma unroll
            for (int i = 0; i < TM; i++)
#pragma unroll
                for (int j = 0; j < TN; j++) acc[i][j] = fmaf(a[i], b[j], acc[i][j]);
        }
        __syncthreads();
    }
#pragma unroll
    for (int i = 0; i < TM; i++)
#pragma unroll
        for (int j = 0; j < TN; j++)
            C[(size_t)(bm + tm + i) * N + bn + tn + j] = acc[i][j];
}

// ---------------------------------------------------------------------------
// RMS norm (+ optional scale, + optional RoPE) per (token, head).
// 128 threads; thread t owns dims t and t+128 (the rotate pair).
// ---------------------------------------------------------------------------
__global__ void norm_rope_kernel(float* __restrict__ data, int nheads,
                                 const float* __restrict__ scale, int do_rope,
                                 const int* __restrict__ positions) {
    const int l = blockIdx.x;
    const int hh = blockIdx.y;
    float* p = data + ((size_t)l * nheads + hh) * HD;
    const int t = threadIdx.x;      // 0..127
    const int lane = t & 31;
    const int wid = t >> 5;

    float a = p[t];
    float b = p[t + 128];
    float ss = a * a + b * b;
#pragma unroll
    for (int off = 16; off > 0; off >>= 1)
        ss += __shfl_xor_sync(0xffffffffu, ss, off);
    __shared__ float red[4];
    if (lane == 0) red[wid] = ss;
    __syncthreads();
    float total = red[0] + red[1] + red[2] + red[3];
    float inv = rsqrtf(total * (1.0f / HD) + 1e-6f);

    float xa = a * inv, xb = b * inv;
    if (scale) { xa *= scale[t]; xb *= scale[t + 128]; }

    if (do_rope) {
        float pos = (float)positions[l];
        float ts = powf(10000.0f, 2.0f * (float)t / (float)HD);
        float ang = pos / ts;
        float sn = sinf(ang), cs = cosf(ang);
        p[t]       = xa * cs - xb * sn;
        p[t + 128] = xb * cs + xa * sn;
    } else {
        p[t] = xa;
        p[t + 128] = xb;
    }
}

// ---------------------------------------------------------------------------
// Sliding-window causal attention, warp-per-query.
// Block = 256 threads (8 warps) -> 8 consecutive queries for one head.
// Lane owns 8 contiguous dims (two float4). Online softmax over the window.
// ---------------------------------------------------------------------------
__global__ void attn_kernel(const float* __restrict__ q,
                            const float* __restrict__ k,
                            const float* __restrict__ v,
                            float* __restrict__ att) {
    const int warp = threadIdx.x >> 5;
    const int lane = threadIdx.x & 31;
    const int qi = blockIdx.x * 8 + warp;
    const int h = blockIdx.y;
    const int kvh = h / (NH / NKVH);

    const float4* qp = (const float4*)(q + ((size_t)qi * NH + h) * HD);
    float4 q0 = qp[lane * 2];
    float4 q1 = qp[lane * 2 + 1];

    float m = -1e30f, lsum = 0.f;
    float4 o0 = {0.f, 0.f, 0.f, 0.f};
    float4 o1 = {0.f, 0.f, 0.f, 0.f};

    int js = qi - (WINDOW - 1);
    if (js < 0) js = 0;

    for (int j = js; j <= qi; j++) {
        const float4* kp = (const float4*)(k + ((size_t)j * NKVH + kvh) * HD);
        float4 k0 = kp[lane * 2];
        float4 k1 = kp[lane * 2 + 1];
        float s = q0.x * k0.x + q0.y * k0.y + q0.z * k0.z + q0.w * k0.w
                + q1.x * k1.x + q1.y * k1.y + q1.z * k1.z + q1.w * k1.w;
#pragma unroll
        for (int off = 16; off > 0; off >>= 1)
            s += __shfl_xor_sync(0xffffffffu, s, off);

        float nm = fmaxf(m, s);
        float corr = __expf(m - nm);
        float pp = __expf(s - nm);
        m = nm;
        lsum = lsum * corr + pp;

        const float4* vp = (const float4*)(v + ((size_t)j * NKVH + kvh) * HD);
        float4 v0 = vp[lane * 2];
        float4 v1 = vp[lane * 2 + 1];
        o0.x = o0.x * corr + pp * v0.x;
        o0.y = o0.y * corr + pp * v0.y;
        o0.z = o0.z * corr + pp * v0.z;
        o0.w = o0.w * corr + pp * v0.w;
        o1.x = o1.x * corr + pp * v1.x;
        o1.y = o1.y * corr + pp * v1.y;
        o1.z = o1.z * corr + pp * v1.z;
        o1.w = o1.w * corr + pp * v1.w;
    }

    float invl = 1.0f / lsum;
    o0.x *= invl; o0.y *= invl; o0.z *= invl; o0.w *= invl;
    o1.x *= invl; o1.y *= invl; o1.z *= invl; o1.w *= invl;

    float4* op = (float4*)(att + ((size_t)qi * NH + h) * HD);
    op[lane * 2] = o0;
    op[lane * 2 + 1] = o1;
}

// ---------------------------------------------------------------------------
extern "C" void kernel_launch(void* const* d_in, const int* in_sizes, int n_in,
                              void* d_out, int out_size) {
    const float* x        = (const float*)d_in[0];
    const int* positions  = (const int*)d_in[1];
    const float* Wq       = (const float*)d_in[2];
    const float* Wk       = (const float*)d_in[3];
    const float* Wv       = (const float*)d_in[4];
    const float* Wo       = (const float*)d_in[5];
    const float* q_scale  = (const float*)d_in[6];
    const float* k_scale  = (const float*)d_in[7];
    float* out            = (float*)d_out;

    float *q, *k, *v, *att;
    cudaGetSymbolAddress((void**)&q, g_q);
    cudaGetSymbolAddress((void**)&k, g_k);
    cudaGetSymbolAddress((void**)&v, g_v);
    cudaGetSymbolAddress((void**)&att, g_att);

    // Projections
    gemm_kernel<<<dim3(D_MODEL / 64, L_SEQ / 64), 256>>>(x, Wq, q, L_SEQ, D_MODEL, D_MODEL);
    gemm_kernel<<<dim3((NKVH * HD) / 64, L_SEQ / 64), 256>>>(x, Wk, k, L_SEQ, NKVH * HD, D_MODEL);
    gemm_kernel<<<dim3((NKVH * HD) / 64, L_SEQ / 64), 256>>>(x, Wv, v, L_SEQ, NKVH * HD, D_MODEL);

    // Norm + RoPE
    norm_rope_kernel<<<dim3(L_SEQ, NH), 128>>>(q, NH, q_scale, 1, positions);
    norm_rope_kernel<<<dim3(L_SEQ, NKVH), 128>>>(k, NKVH, k_scale, 1, positions);
    norm_rope_kernel<<<dim3(L_SEQ, NKVH), 128>>>(v, NKVH, nullptr, 0, positions);

    // Attention
    attn_kernel<<<dim3(L_SEQ / 8, NH), 256>>>(q, k, v, att);

    // Output projection
    gemm_kernel<<<dim3(D_MODEL / 64, L_SEQ / 64), 256>>>(att, Wo, out, L_SEQ, D_MODEL, D_MODEL);
}

// round 3
// speedup vs baseline: 1.6795x; 1.6795x over previous
#include <cuda_runtime.h>
#include <cuda_bf16.h>
#include <math.h>
#include <stdint.h>

#define L_SEQ 4096
#define D_MODEL 2048
#define NH 8
#define NKVH 2
#define HD 256
#define WINDOW 512
#define NQKV 3072  // 2048 q + 512 k + 512 v

// ---------------- scratch (device globals; no cudaMalloc allowed) ----------
__device__ __nv_bfloat16 g_ah[L_SEQ * D_MODEL];        // A hi (x, later att)
__device__ __nv_bfloat16 g_al[L_SEQ * D_MODEL];        // A lo
__device__ __nv_bfloat16 g_wqkv_h[NQKV * D_MODEL];     // [Wq|Wk|Wv]^T hi, (N,K)
__device__ __nv_bfloat16 g_wqkv_l[NQKV * D_MODEL];
__device__ __nv_bfloat16 g_wo_h[D_MODEL * D_MODEL];    // Wo^T hi
__device__ __nv_bfloat16 g_wo_l[D_MODEL * D_MODEL];
__device__ float g_qkv[L_SEQ * NQKV];                  // fused qkv activations
__device__ float g_att[L_SEQ * D_MODEL];               // attention output

static __device__ __forceinline__ uint32_t smem_u32(const void* p) {
    uint32_t a;
    asm("{ .reg .u64 t; cvta.to.shared.u64 t, %1; cvt.u32.u64 %0, t; }"
        : "=r"(a) : "l"(p));
    return a;
}

// ---------------- split fp32 -> bf16 hi/lo (vector x4) ---------------------
__global__ void split_kernel(const float* __restrict__ in,
                             __nv_bfloat16* __restrict__ hi,
                             __nv_bfloat16* __restrict__ lo, int n4) {
    int i = blockIdx.x * blockDim.x + threadIdx.x;
    if (i >= n4) return;
    float4 a = ((const float4*)in)[i];
    __nv_bfloat16 h0 = __float2bfloat16(a.x);
    __nv_bfloat16 h1 = __float2bfloat16(a.y);
    __nv_bfloat16 h2 = __float2bfloat16(a.z);
    __nv_bfloat16 h3 = __float2bfloat16(a.w);
    __nv_bfloat16 l0 = __float2bfloat16(a.x - __bfloat162float(h0));
    __nv_bfloat16 l1 = __float2bfloat16(a.y - __bfloat162float(h1));
    __nv_bfloat16 l2 = __float2bfloat16(a.z - __bfloat162float(h2));
    __nv_bfloat16 l3 = __float2bfloat16(a.w - __bfloat162float(h3));
    __nv_bfloat162* ph = (__nv_bfloat162*)hi;
    __nv_bfloat162* pl = (__nv_bfloat162*)lo;
    ph[i * 2]     = __nv_bfloat162{h0, h1};
    ph[i * 2 + 1] = __nv_bfloat162{h2, h3};
    pl[i * 2]     = __nv_bfloat162{l0, l1};
    pl[i * 2 + 1] = __nv_bfloat162{l2, l3};
}

// ---------------- transpose + split: W(K=2048, N) -> WT(N, 2048) hi/lo -----
__global__ void tsplit_kernel(const float* __restrict__ W,
                              __nv_bfloat16* __restrict__ th,
                              __nv_bfloat16* __restrict__ tl,
                              int N, int roff) {
    __shared__ float s[32][33];
    int n0 = blockIdx.x * 32, k0 = blockIdx.y * 32;
    int tx = threadIdx.x, ty = threadIdx.y;  // 32 x 8
#pragma unroll
    for (int r = 0; r < 4; r++)
        s[ty + r * 8][tx] = W[(size_t)(k0 + ty + r * 8) * N + n0 + tx];
    __syncthreads();
#pragma unroll
    for (int r = 0; r < 4; r++) {
        int n = n0 + ty + r * 8;
        float a = s[tx][ty + r * 8];
        __nv_bfloat16 h = __float2bfloat16(a);
        __nv_bfloat16 l = __float2bfloat16(a - __bfloat162float(h));
        th[(size_t)(roff + n) * D_MODEL + k0 + tx] = h;
        tl[(size_t)(roff + n) * D_MODEL + k0 + tx] = l;
    }
}

// ---------------- HMMA bf16x3 GEMM: C[M,N] = A @ B^T ------------------------
// A hi/lo: (M, K) K-major bf16.  B hi/lo: (N, K) K-major bf16.  C fp32.
// 128x128 CTA tile, BK=32, double-buffered cp.async, 8 warps (64x32 each).
#define OPSTRIDE 80                 // bytes per smem row (40 bf16, padded)
#define OP_TILE_B (128 * OPSTRIDE)  // 10240 B per operand tile
#define BUF_BYTES (4 * OP_TILE_B)   // Ah, Al, Bh, Bl
#define GEMM_SMEM (2 * BUF_BYTES)   // 81920 B

#define LDM4(r, addr)                                                          \
    asm volatile("ldmatrix.sync.aligned.m8n8.x4.shared.b16 {%0,%1,%2,%3}, [%4];"\
        : "=r"((r)[0]), "=r"((r)[1]), "=r"((r)[2]), "=r"((r)[3]) : "r"(addr))

#define MMA16816(c, a, b0v, b1v)                                               \
    asm volatile("mma.sync.aligned.m16n8k16.row.col.f32.bf16.bf16.f32 "        \
        "{%0,%1,%2,%3}, {%4,%5,%6,%7}, {%8,%9}, {%0,%1,%2,%3};"                \
        : "+f"((c)[0]), "+f"((c)[1]), "+f"((c)[2]), "+f"((c)[3])               \
        : "r"((a)[0]), "r"((a)[1]), "r"((a)[2]), "r"((a)[3]),                  \
          "r"(b0v), "r"(b1v))

__global__ void __launch_bounds__(256, 1)
gemm_hmma(const __nv_bfloat16* __restrict__ Ah, const __nv_bfloat16* __restrict__ Al,
          const __nv_bfloat16* __restrict__ Bh, const __nv_bfloat16* __restrict__ Bl,
          float* __restrict__ C, int K, int ldc) {
    extern __shared__ __align__(128) char gsm[];
    const int tid = threadIdx.x;
    const int lane = tid & 31;
    const int wid = tid >> 5;
    const int wm = (wid & 1) * 64;      // warp M offset in tile
    const int wn = (wid >> 1) * 32;     // warp N offset in tile
    const int bm = blockIdx.y * 128;
    const int bn = blockIdx.x * 128;
    const uint32_t sbase = smem_u32(gsm);

    const __nv_bfloat16* gptr[4] = {
        Ah + (size_t)bm * K, Al + (size_t)bm * K,
        Bh + (size_t)bn * K, Bl + (size_t)bn * K };

    // per-thread staging map: 8 x 16B segments per chunk
    // s = it*256 + tid ; op = s>>9 ; t = s&511 ; row = t>>2 ; cc = t&3
    float acc[4][4][4];
#pragma unroll
    for (int a = 0; a < 4; a++)
#pragma unroll
        for (int b = 0; b < 4; b++)
#pragma unroll
            for (int c = 0; c < 4; c++) acc[a][b][c] = 0.f;

    // ldmatrix lane address offsets
    const uint32_t a_off = (uint32_t)(lane & 15) * OPSTRIDE + ((lane & 16) ? 16u : 0u);
    const uint32_t b_off = (uint32_t)(((lane & 16) ? 8 : 0) + (lane & 7)) * OPSTRIDE
                         + ((lane & 8) ? 16u : 0u);

    const int nch = K >> 5;

    // ---- stage chunk 0
    {
        const int k0 = 0;
        uint32_t dbase = sbase;
#pragma unroll
        for (int it = 0; it < 8; it++) {
            int s = it * 256 + tid;
            int op = s >> 9, t = s & 511;
            int row = t >> 2, cc = t & 3;
            const __nv_bfloat16* src = gptr[op] + (size_t)row * K + k0 + cc * 8;
            uint32_t dst = dbase + op * OP_TILE_B + row * OPSTRIDE + cc * 16;
            asm volatile("cp.async.cg.shared.global [%0], [%1], 16;"
                         :: "r"(dst), "l"(src) : "memory");
        }
        asm volatile("cp.async.commit_group;" ::: "memory");
    }

    for (int c = 0; c < nch; c++) {
        if (c + 1 < nch) {
            const int k0 = (c + 1) << 5;
            uint32_t dbase = sbase + (((c + 1) & 1) ? BUF_BYTES : 0);
#pragma unroll
            for (int it = 0; it < 8; it++) {
                int s = it * 256 + tid;
                int op = s >> 9, t = s & 511;
                int row = t >> 2, cc = t & 3;
                const __nv_bfloat16* src = gptr[op] + (size_t)row * K + k0 + cc * 8;
                uint32_t dst = dbase + op * OP_TILE_B + row * OPSTRIDE + cc * 16;
                asm volatile("cp.async.cg.shared.global [%0], [%1], 16;"
                             :: "r"(dst), "l"(src) : "memory");
            }
            asm volatile("cp.async.commit_group;" ::: "memory");
            asm volatile("cp.async.wait_group 1;" ::: "memory");
        } else {
            asm volatile("cp.async.wait_group 0;" ::: "memory");
        }
        __syncthreads();

        const uint32_t dbase = sbase + ((c & 1) ? BUF_BYTES : 0);
#pragma unroll
        for (int ks = 0; ks < 2; ks++) {
            const uint32_t kb = ks * 32;
            uint32_t ahf[4][4], alf[4][4], bhf[2][4], blf[2][4];
#pragma unroll
            for (int mt = 0; mt < 4; mt++) {
                uint32_t ra = (wm + mt * 16) * OPSTRIDE + kb + a_off;
                LDM4(ahf[mt], dbase + ra);
                LDM4(alf[mt], dbase + OP_TILE_B + ra);
            }
#pragma unroll
            for (int np = 0; np < 2; np++) {
                uint32_t rb = (wn + np * 16) * OPSTRIDE + kb + b_off;
                LDM4(bhf[np], dbase + 2 * OP_TILE_B + rb);
                LDM4(blf[np], dbase + 3 * OP_TILE_B + rb);
            }
#pragma unroll
            for (int mt = 0; mt < 4; mt++)
#pragma unroll
                for (int nt = 0; nt < 4; nt++) {
                    const int np = nt >> 1, sel = (nt & 1) * 2;
                    MMA16816(acc[mt][nt], ahf[mt], bhf[np][sel], bhf[np][sel + 1]);
                    MMA16816(acc[mt][nt], ahf[mt], blf[np][sel], blf[np][sel + 1]);
                    MMA16816(acc[mt][nt], alf[mt], bhf[np][sel], bhf[np][sel + 1]);
                }
        }
        __syncthreads();
    }

    // ---- epilogue: write accumulators
#pragma unroll
    for (int mt = 0; mt < 4; mt++) {
        int r0 = bm + wm + mt * 16 + (lane >> 2);
#pragma unroll
        for (int nt = 0; nt < 4; nt++) {
            int c0 = bn + wn + nt * 8 + (lane & 3) * 2;
            *(float2*)(C + (size_t)r0 * ldc + c0) =
                make_float2(acc[mt][nt][0], acc[mt][nt][1]);
            *(float2*)(C + (size_t)(r0 + 8) * ldc + c0) =
                make_float2(acc[mt][nt][2], acc[mt][nt][3]);
        }
    }
}

// ---------------- RMS norm (+scale, +RoPE) on strided qkv ------------------
__global__ void norm_rope_kernel(float* __restrict__ data, int rowstride, int headoff,
                                 const float* __restrict__ scale, int do_rope,
                                 const int* __restrict__ positions) {
    const int l = blockIdx.x;
    const int hh = blockIdx.y;
    float* p = data + (size_t)l * rowstride + headoff + hh * HD;
    const int t = threadIdx.x;  // 0..127
    const int lane = t & 31;
    const int wid = t >> 5;

    float a = p[t];
    float b = p[t + 128];
    float ss = a * a + b * b;
#pragma unroll
    for (int off = 16; off > 0; off >>= 1)
        ss += __shfl_xor_sync(0xffffffffu, ss, off);
    __shared__ float red[4];
    if (lane == 0) red[wid] = ss;
    __syncthreads();
    float total = red[0] + red[1] + red[2] + red[3];
    float inv = rsqrtf(total * (1.0f / HD) + 1e-6f);

    float xa = a * inv, xb = b * inv;
    if (scale) { xa *= scale[t]; xb *= scale[t + 128]; }

    if (do_rope) {
        float pos = (float)positions[l];
        float ts = powf(10000.0f, 2.0f * (float)t / (float)HD);
        float ang = pos / ts;
        float sn = sinf(ang), cs = cosf(ang);
        p[t]       = xa * cs - xb * sn;
        p[t + 128] = xb * cs + xa * sn;
    } else {
        p[t] = xa;
        p[t + 128] = xb;
    }
}

// ---------------- sliding-window attention (warp per query) ----------------
__global__ void attn_kernel(const float* __restrict__ qkv, float* __restrict__ att) {
    const int warp = threadIdx.x >> 5;
    const int lane = threadIdx.x & 31;
    const int qi = blockIdx.x * 8 + warp;
    const int h = blockIdx.y;
    const int kvh = h / (NH / NKVH);

    const float4* qp = (const float4*)(qkv + (size_t)qi * NQKV + h * HD);
    float4 q0 = qp[lane * 2];
    float4 q1 = qp[lane * 2 + 1];

    const float* kbase = qkv + 2048 + kvh * HD;
    const float* vbase = qkv + 2560 + kvh * HD;

    float m = -1e30f, lsum = 0.f;
    float4 o0 = {0.f, 0.f, 0.f, 0.f};
    float4 o1 = {0.f, 0.f, 0.f, 0.f};

    int js = qi - (WINDOW - 1);
    if (js < 0) js = 0;

    for (int j = js; j <= qi; j++) {
        const float4* kp = (const float4*)(kbase + (size_t)j * NQKV);
        float4 k0 = kp[lane * 2];
        float4 k1 = kp[lane * 2 + 1];
        float s = q0.x * k0.x + q0.y * k0.y + q0.z * k0.z + q0.w * k0.w
                + q1.x * k1.x + q1.y * k1.y + q1.z * k1.z + q1.w * k1.w;
#pragma unroll
        for (int off = 16; off > 0; off >>= 1)
            s += __shfl_xor_sync(0xffffffffu, s, off);

        float nm = fmaxf(m, s);
        float corr = __expf(m - nm);
        float pp = __expf(s - nm);
        m = nm;
        lsum = lsum * corr + pp;

        const float4* vp = (const float4*)(vbase + (size_t)j * NQKV);
        float4 v0 = vp[lane * 2];
        float4 v1 = vp[lane * 2 + 1];
        o0.x = o0.x * corr + pp * v0.x;
        o0.y = o0.y * corr + pp * v0.y;
        o0.z = o0.z * corr + pp * v0.z;
        o0.w = o0.w * corr + pp * v0.w;
        o1.x = o1.x * corr + pp * v1.x;
        o1.y = o1.y * corr + pp * v1.y;
        o1.z = o1.z * corr + pp * v1.z;
        o1.w = o1.w * corr + pp * v1.w;
    }

    float invl = 1.0f / lsum;
    o0.x *= invl; o0.y *= invl; o0.z *= invl; o0.w *= invl;
    o1.x *= invl; o1.y *= invl; o1.z *= invl; o1.w *= invl;

    float4* op = (float4*)(att + (size_t)qi * D_MODEL + h * HD);
    op[lane * 2] = o0;
    op[lane * 2 + 1] = o1;
}

// ---------------------------------------------------------------------------
extern "C" void kernel_launch(void* const* d_in, const int* in_sizes, int n_in,
                              void* d_out, int out_size) {
    const float* x       = (const float*)d_in[0];
    const int* positions = (const int*)d_in[1];
    const float* Wq      = (const float*)d_in[2];
    const float* Wk      = (const float*)d_in[3];
    const float* Wv      = (const float*)d_in[4];
    const float* Wo      = (const float*)d_in[5];
    const float* q_scale = (const float*)d_in[6];
    const float* k_scale = (const float*)d_in[7];
    float* out           = (float*)d_out;

    __nv_bfloat16 *ah, *al, *wqh, *wql, *woh, *wol;
    float *qkv, *att;
    cudaGetSymbolAddress((void**)&ah, g_ah);
    cudaGetSymbolAddress((void**)&al, g_al);
    cudaGetSymbolAddress((void**)&wqh, g_wqkv_h);
    cudaGetSymbolAddress((void**)&wql, g_wqkv_l);
    cudaGetSymbolAddress((void**)&woh, g_wo_h);
    cudaGetSymbolAddress((void**)&wol, g_wo_l);
    cudaGetSymbolAddress((void**)&qkv, g_qkv);
    cudaGetSymbolAddress((void**)&att, g_att);

    static int smem_set = 0;
    if (!smem_set) {
        cudaFuncSetAttribute(gemm_hmma, cudaFuncAttributeMaxDynamicSharedMemorySize,
                             GEMM_SMEM);
        smem_set = 1;
    }

    // weights: transpose + bf16 split  (W(K,N) -> WT(N,K) hi/lo)
    tsplit_kernel<<<dim3(2048 / 32, 64), dim3(32, 8)>>>(Wq, wqh, wql, 2048, 0);
    tsplit_kernel<<<dim3(512 / 32, 64), dim3(32, 8)>>>(Wk, wqh, wql, 512, 2048);
    tsplit_kernel<<<dim3(512 / 32, 64), dim3(32, 8)>>>(Wv, wqh, wql, 512, 2560);
    tsplit_kernel<<<dim3(2048 / 32, 64), dim3(32, 8)>>>(Wo, woh, wol, 2048, 0);

    // activations: bf16 split
    int n4 = (L_SEQ * D_MODEL) / 4;
    split_kernel<<<(n4 + 255) / 256, 256>>>(x, ah, al, n4);

    // fused QKV projection: (4096 x 3072) = x @ [Wq|Wk|Wv]
    gemm_hmma<<<dim3(NQKV / 128, L_SEQ / 128), 256, GEMM_SMEM>>>(
        ah, al, wqh, wql, qkv, D_MODEL, NQKV);

    // norm + rope
    norm_rope_kernel<<<dim3(L_SEQ, NH), 128>>>(qkv, NQKV, 0, q_scale, 1, positions);
    norm_rope_kernel<<<dim3(L_SEQ, NKVH), 128>>>(qkv, NQKV, 2048, k_scale, 1, positions);
    norm_rope_kernel<<<dim3(L_SEQ, NKVH), 128>>>(qkv, NQKV, 2560, nullptr, 0, positions);

    // attention
    attn_kernel<<<dim3(L_SEQ / 8, NH), 256>>>(qkv, att);

    // output projection: out = att @ Wo
    split_kernel<<<(n4 + 255) / 256, 256>>>(att, ah, al, n4);
    gemm_hmma<<<dim3(D_MODEL / 128, L_SEQ / 128), 256, GEMM_SMEM>>>(
        ah, al, woh, wol, out, D_MODEL, D_MODEL);
}

// round 5
// speedup vs baseline: 3.9675x; 2.3623x over previous
#include <cuda_runtime.h>
#include <cuda_bf16.h>
#include <math.h>
#include <stdint.h>

#define L_SEQ 4096
#define D_MODEL 2048
#define NH 8
#define NKVH 2
#define HD 256
#define WINDOW 512
#define NQKV 3072  // 2048 q + 512 k + 512 v

// ---------------- scratch (device globals; no cudaMalloc allowed) ----------
__device__ __nv_bfloat16 g_ah[L_SEQ * D_MODEL];        // A hi (x, later attn O)
__device__ __nv_bfloat16 g_al[L_SEQ * D_MODEL];        // A lo
__device__ __nv_bfloat16 g_wqkv_h[NQKV * D_MODEL];     // [Wq|Wk|Wv]^T hi, (N,K)
__device__ __nv_bfloat16 g_wqkv_l[NQKV * D_MODEL];
__device__ __nv_bfloat16 g_wo_h[D_MODEL * D_MODEL];    // Wo^T hi
__device__ __nv_bfloat16 g_wo_l[D_MODEL * D_MODEL];
__device__ float g_qkv[L_SEQ * NQKV];                  // fused qkv activations
// head-major split q/k/v for attention
__device__ __nv_bfloat16 g_qh[NH * L_SEQ * HD];
__device__ __nv_bfloat16 g_ql[NH * L_SEQ * HD];
__device__ __nv_bfloat16 g_kh[NKVH * L_SEQ * HD];
__device__ __nv_bfloat16 g_kl[NKVH * L_SEQ * HD];
__device__ __nv_bfloat16 g_vh[NKVH * L_SEQ * HD];
__device__ __nv_bfloat16 g_vl[NKVH * L_SEQ * HD];

static __device__ __forceinline__ uint32_t smem_u32(const void* p) {
    uint32_t a;
    asm("{ .reg .u64 t; cvta.to.shared.u64 t, %1; cvt.u32.u64 %0, t; }"
        : "=r"(a) : "l"(p));
    return a;
}

#define CPA16(dst, src)                                                        \
    asm volatile("cp.async.cg.shared.global [%0], [%1], 16;"                   \
                 :: "r"(dst), "l"(src) : "memory")
#define CPA_COMMIT asm volatile("cp.async.commit_group;" ::: "memory")
#define CPA_WAIT0  asm volatile("cp.async.wait_group 0;" ::: "memory")

#define LDM4(r, addr)                                                          \
    asm volatile("ldmatrix.sync.aligned.m8n8.x4.shared.b16 {%0,%1,%2,%3}, [%4];"\
        : "=r"((r)[0]), "=r"((r)[1]), "=r"((r)[2]), "=r"((r)[3]) : "r"(addr))

#define LDM4T(r, addr)                                                         \
    asm volatile("ldmatrix.sync.aligned.m8n8.x4.trans.shared.b16 {%0,%1,%2,%3}, [%4];"\
        : "=r"((r)[0]), "=r"((r)[1]), "=r"((r)[2]), "=r"((r)[3]) : "r"(addr))

#define MMA16816(c, a, b0v, b1v)                                               \
    asm volatile("mma.sync.aligned.m16n8k16.row.col.f32.bf16.bf16.f32 "        \
        "{%0,%1,%2,%3}, {%4,%5,%6,%7}, {%8,%9}, {%0,%1,%2,%3};"                \
        : "+f"((c)[0]), "+f"((c)[1]), "+f"((c)[2]), "+f"((c)[3])               \
        : "r"((a)[0]), "r"((a)[1]), "r"((a)[2]), "r"((a)[3]),                  \
          "r"(b0v), "r"(b1v))

// ---------------- split fp32 -> bf16 hi/lo (vector x4) ---------------------
__global__ void split_kernel(const float* __restrict__ in,
                             __nv_bfloat16* __restrict__ hi,
                             __nv_bfloat16* __restrict__ lo, int n4) {
    int i = blockIdx.x * blockDim.x + threadIdx.x;
    if (i >= n4) return;
    float4 a = ((const float4*)in)[i];
    __nv_bfloat16 h0 = __float2bfloat16(a.x);
    __nv_bfloat16 h1 = __float2bfloat16(a.y);
    __nv_bfloat16 h2 = __float2bfloat16(a.z);
    __nv_bfloat16 h3 = __float2bfloat16(a.w);
    __nv_bfloat16 l0 = __float2bfloat16(a.x - __bfloat162float(h0));
    __nv_bfloat16 l1 = __float2bfloat16(a.y - __bfloat162float(h1));
    __nv_bfloat16 l2 = __float2bfloat16(a.z - __bfloat162float(h2));
    __nv_bfloat16 l3 = __float2bfloat16(a.w - __bfloat162float(h3));
    __nv_bfloat162* ph = (__nv_bfloat162*)hi;
    __nv_bfloat162* pl = (__nv_bfloat162*)lo;
    ph[i * 2]     = __nv_bfloat162{h0, h1};
    ph[i * 2 + 1] = __nv_bfloat162{h2, h3};
    pl[i * 2]     = __nv_bfloat162{l0, l1};
    pl[i * 2 + 1] = __nv_bfloat162{l2, l3};
}

// ---------------- transpose + split: W(K=2048, N) -> WT(N, 2048) hi/lo -----
__global__ void tsplit_kernel(const float* __restrict__ W,
                              __nv_bfloat16* __restrict__ th,
                              __nv_bfloat16* __restrict__ tl,
                              int N, int roff) {
    __shared__ float s[32][33];
    int n0 = blockIdx.x * 32, k0 = blockIdx.y * 32;
    int tx = threadIdx.x, ty = threadIdx.y;  // 32 x 8
#pragma unroll
    for (int r = 0; r < 4; r++)
        s[ty + r * 8][tx] = W[(size_t)(k0 + ty + r * 8) * N + n0 + tx];
    __syncthreads();
#pragma unroll
    for (int r = 0; r < 4; r++) {
        int n = n0 + ty + r * 8;
        float a = s[tx][ty + r * 8];
        __nv_bfloat16 h = __float2bfloat16(a);
        __nv_bfloat16 l = __float2bfloat16(a - __bfloat162float(h));
        th[(size_t)(roff + n) * D_MODEL + k0 + tx] = h;
        tl[(size_t)(roff + n) * D_MODEL + k0 + tx] = l;
    }
}

// ---------------- HMMA bf16x3 GEMM: C[M,N] = A @ B^T ------------------------
#define OPSTRIDE 80
#define OP_TILE_B (128 * OPSTRIDE)
#define BUF_BYTES (4 * OP_TILE_B)
#define GEMM_SMEM (2 * BUF_BYTES)

__global__ void __launch_bounds__(256, 1)
gemm_hmma(const __nv_bfloat16* __restrict__ Ah, const __nv_bfloat16* __restrict__ Al,
          const __nv_bfloat16* __restrict__ Bh, const __nv_bfloat16* __restrict__ Bl,
          float* __restrict__ C, int K, int ldc) {
    extern __shared__ __align__(128) char gsm[];
    const int tid = threadIdx.x;
    const int lane = tid & 31;
    const int wid = tid >> 5;
    const int wm = (wid & 1) * 64;
    const int wn = (wid >> 1) * 32;
    const int bm = blockIdx.y * 128;
    const int bn = blockIdx.x * 128;
    const uint32_t sbase = smem_u32(gsm);

    const __nv_bfloat16* gptr[4] = {
        Ah + (size_t)bm * K, Al + (size_t)bm * K,
        Bh + (size_t)bn * K, Bl + (size_t)bn * K };

    float acc[4][4][4];
#pragma unroll
    for (int a = 0; a < 4; a++)
#pragma unroll
        for (int b = 0; b < 4; b++)
#pragma unroll
            for (int c = 0; c < 4; c++) acc[a][b][c] = 0.f;

    const uint32_t a_off = (uint32_t)(lane & 15) * OPSTRIDE + ((lane & 16) ? 16u : 0u);
    const uint32_t b_off = (uint32_t)(((lane & 16) ? 8 : 0) + (lane & 7)) * OPSTRIDE
                         + ((lane & 8) ? 16u : 0u);

    const int nch = K >> 5;
    {
        uint32_t dbase = sbase;
#pragma unroll
        for (int it = 0; it < 8; it++) {
            int s = it * 256 + tid;
            int op = s >> 9, t = s & 511;
            int row = t >> 2, cc = t & 3;
            const __nv_bfloat16* src = gptr[op] + (size_t)row * K + cc * 8;
            uint32_t dst = dbase + op * OP_TILE_B + row * OPSTRIDE + cc * 16;
            CPA16(dst, src);
        }
        CPA_COMMIT;
    }

    for (int c = 0; c < nch; c++) {
        if (c + 1 < nch) {
            const int k0 = (c + 1) << 5;
            uint32_t dbase = sbase + (((c + 1) & 1) ? BUF_BYTES : 0);
#pragma unroll
            for (int it = 0; it < 8; it++) {
                int s = it * 256 + tid;
                int op = s >> 9, t = s & 511;
                int row = t >> 2, cc = t & 3;
                const __nv_bfloat16* src = gptr[op] + (size_t)row * K + k0 + cc * 8;
                uint32_t dst = dbase + op * OP_TILE_B + row * OPSTRIDE + cc * 16;
                CPA16(dst, src);
            }
            CPA_COMMIT;
            asm volatile("cp.async.wait_group 1;" ::: "memory");
        } else {
            CPA_WAIT0;
        }
        __syncthreads();

        const uint32_t dbase = sbase + ((c & 1) ? BUF_BYTES : 0);
#pragma unroll
        for (int ks = 0; ks < 2; ks++) {
            const uint32_t kb = ks * 32;
            uint32_t ahf[4][4], alf[4][4], bhf[2][4], blf[2][4];
#pragma unroll
            for (int mt = 0; mt < 4; mt++) {
                uint32_t ra = (wm + mt * 16) * OPSTRIDE + kb + a_off;
                LDM4(ahf[mt], dbase + ra);
                LDM4(alf[mt], dbase + OP_TILE_B + ra);
            }
#pragma unroll
            for (int np = 0; np < 2; np++) {
                uint32_t rb = (wn + np * 16) * OPSTRIDE + kb + b_off;
                LDM4(bhf[np], dbase + 2 * OP_TILE_B + rb);
                LDM4(blf[np], dbase + 3 * OP_TILE_B + rb);
            }
#pragma unroll
            for (int mt = 0; mt < 4; mt++)
#pragma unroll
                for (int nt = 0; nt < 4; nt++) {
                    const int np = nt >> 1, sel = (nt & 1) * 2;
                    MMA16816(acc[mt][nt], ahf[mt], bhf[np][sel], bhf[np][sel + 1]);
                    MMA16816(acc[mt][nt], ahf[mt], blf[np][sel], blf[np][sel + 1]);
                    MMA16816(acc[mt][nt], alf[mt], bhf[np][sel], bhf[np][sel + 1]);
                }
        }
        __syncthreads();
    }

#pragma unroll
    for (int mt = 0; mt < 4; mt++) {
        int r0 = bm + wm + mt * 16 + (lane >> 2);
#pragma unroll
        for (int nt = 0; nt < 4; nt++) {
            int c0 = bn + wn + nt * 8 + (lane & 3) * 2;
            *(float2*)(C + (size_t)r0 * ldc + c0) =
                make_float2(acc[mt][nt][0], acc[mt][nt][1]);
            *(float2*)(C + (size_t)(r0 + 8) * ldc + c0) =
                make_float2(acc[mt][nt][2], acc[mt][nt][3]);
        }
    }
}

// ---------------- RMS norm (+scale, +RoPE) -> split bf16 head-major --------
__global__ void norm_split_kernel(const float* __restrict__ qkv, int headoff,
                                  const float* __restrict__ scale, int do_rope,
                                  const int* __restrict__ positions,
                                  __nv_bfloat16* __restrict__ oh,
                                  __nv_bfloat16* __restrict__ ol) {
    const int l = blockIdx.x;
    const int hh = blockIdx.y;
    const float* p = qkv + (size_t)l * NQKV + headoff + hh * HD;
    const int t = threadIdx.x;  // 0..127
    const int lane = t & 31;
    const int wid = t >> 5;

    float a = p[t];
    float b = p[t + 128];
    float ss = a * a + b * b;
#pragma unroll
    for (int off = 16; off > 0; off >>= 1)
        ss += __shfl_xor_sync(0xffffffffu, ss, off);
    __shared__ float red[4];
    if (lane == 0) red[wid] = ss;
    __syncthreads();
    float total = red[0] + red[1] + red[2] + red[3];
    float inv = rsqrtf(total * (1.0f / HD) + 1e-6f);

    float xa = a * inv, xb = b * inv;
    if (scale) { xa *= scale[t]; xb *= scale[t + 128]; }

    float ya, yb;
    if (do_rope) {
        float pos = (float)positions[l];
        float ts = powf(10000.0f, 2.0f * (float)t / (float)HD);
        float ang = pos / ts;
        float sn = sinf(ang), cs = cosf(ang);
        ya = xa * cs - xb * sn;
        yb = xb * cs + xa * sn;
    } else {
        ya = xa; yb = xb;
    }
    size_t o = ((size_t)hh * L_SEQ + l) * HD;
    __nv_bfloat16 ha = __float2bfloat16(ya);
    __nv_bfloat16 hb = __float2bfloat16(yb);
    oh[o + t]       = ha;
    oh[o + t + 128] = hb;
    ol[o + t]       = __float2bfloat16(ya - __bfloat162float(ha));
    ol[o + t + 128] = __float2bfloat16(yb - __bfloat162float(hb));
}

// ---------------- tensor-core sliding-window flash attention ---------------
// CTA: 64 queries x 1 head. 8 warps = 4 qgroups(16q) x 2 d-halves(128d).
// K-tile = 16 keys. bf16x3 split for both S=Q.K^T and O=P.V.
#define QB 64
#define KT 16
// smem: Qh 32K | Ql 32K | Kh 8K | Kl 8K | Vh 8K | Vl 8K = 96K
#define ATT_SMEM (96 * 1024)

__global__ void __launch_bounds__(256, 1)
attn_tc(const __nv_bfloat16* __restrict__ qhp, const __nv_bfloat16* __restrict__ qlp,
        const __nv_bfloat16* __restrict__ khp, const __nv_bfloat16* __restrict__ klp,
        const __nv_bfloat16* __restrict__ vhp, const __nv_bfloat16* __restrict__ vlp,
        __nv_bfloat16* __restrict__ oh, __nv_bfloat16* __restrict__ ol) {
    extern __shared__ __align__(128) char asmem[];
    const int tid = threadIdx.x, lane = tid & 31, wid = tid >> 5;
    const int qb = blockIdx.x, h = blockIdx.y;
    const int kvh = h / (NH / NKVH);
    const int Q0 = qb * QB;
    const int qg = wid >> 1;   // 0..3
    const int dh = wid & 1;    // d half
    const uint32_t sb = smem_u32(asmem);
    const uint32_t sQ = sb;                 // hi; lo at +32768
    const uint32_t sKV = sb + 65536;        // Kh | Kl(+8192) | Vh(+16384) | Vl(+24576)

    // ---- stage Q (64 rows x 256d, hi+lo) with xor swizzle
#pragma unroll
    for (int i = 0; i < 16; i++) {
        int gid = i * 256 + tid;
        int mat = gid >> 11;           // 0=hi 1=lo
        int t = gid & 2047;
        int row = t >> 5, g = t & 31;
        const __nv_bfloat16* src = (mat ? qlp : qhp)
            + ((size_t)h * L_SEQ + Q0 + row) * HD + g * 8;
        uint32_t dst = sQ + mat * 32768 + row * 512 + ((g ^ (row & 7)) << 4);
        CPA16(dst, src);
    }
    CPA_COMMIT;

    float m0 = -1e9f, m1 = -1e9f;   // row lane>>2, +8
    float l0 = 0.f, l1 = 0.f;
    float O[16][4];
#pragma unroll
    for (int nt = 0; nt < 16; nt++)
#pragma unroll
        for (int e = 0; e < 4; e++) O[nt][e] = 0.f;

    int kstart = Q0 - (WINDOW - 1);
    if (kstart < 0) kstart = 0;
    kstart &= ~(KT - 1);
    const int kend = Q0 + QB;
    const int R0 = Q0 + qg * 16;

    // lane addressing constants
    const int qa_r = ((lane >> 3) & 1) * 8 + (lane & 7);   // A-frag row-in-16
    const int qa_gs = (lane >> 4);                          // A-frag granule add
    const int kb_r = ((lane >> 4) & 1) * 8 + (lane & 7);   // B-frag key row
    const int kb_gs = ((lane >> 3) & 1);                    // B-frag granule add
    const int vb_r = ((lane >> 3) & 1) * 8 + (lane & 7);   // V trans row
    const int vb_gs = (lane >> 4);

    CPA_WAIT0;
    __syncthreads();

    for (int kt = kstart; kt < kend; kt += KT) {
        // ---- stage K/V tile (4 mats x 16 rows x 32 granules)
        __syncthreads();
#pragma unroll
        for (int i = 0; i < 8; i++) {
            int gid = i * 256 + tid;
            int mat = gid >> 9;
            int t = gid & 511;
            int row = t >> 5, g = t & 31;
            const __nv_bfloat16* srcb =
                (mat == 0) ? khp : (mat == 1) ? klp : (mat == 2) ? vhp : vlp;
            const __nv_bfloat16* src = srcb
                + ((size_t)kvh * L_SEQ + kt + row) * HD + g * 8;
            uint32_t dst = sKV + mat * 8192 + row * 512 + ((g ^ (row & 7)) << 4);
            CPA16(dst, src);
        }
        CPA_COMMIT;
        CPA_WAIT0;
        __syncthreads();

        // ---- S = Q.K^T (bf16x3), 16q x 16k per warp
        float S[2][4];
#pragma unroll
        for (int nt = 0; nt < 2; nt++)
#pragma unroll
            for (int e = 0; e < 4; e++) S[nt][e] = 0.f;

#pragma unroll
        for (int ks = 0; ks < 16; ks++) {
            uint32_t qa[4], qal[4], kb[4], kbl[4];
            int qrow = qg * 16 + qa_r;
            int qg_g = ks * 2 + qa_gs;
            uint32_t qaddr = sQ + qrow * 512 + (((qg_g) ^ (qrow & 7)) << 4);
            LDM4(qa, qaddr);
            LDM4(qal, qaddr + 32768);
            int kg_g = ks * 2 + kb_gs;
            uint32_t kaddr = sKV + kb_r * 512 + (((kg_g) ^ (kb_r & 7)) << 4);
            LDM4(kb, kaddr);
            LDM4(kbl, kaddr + 8192);
            MMA16816(S[0], qa, kb[0], kb[1]);
            MMA16816(S[0], qa, kbl[0], kbl[1]);
            MMA16816(S[0], qal, kb[0], kb[1]);
            MMA16816(S[1], qa, kb[2], kb[3]);
            MMA16816(S[1], qa, kbl[2], kbl[3]);
            MMA16816(S[1], qal, kb[2], kb[3]);
        }

        // ---- mask
        const bool fullvalid = (kt + KT - 1 <= R0) && (kt >= R0 + 15 - (WINDOW - 1));
        if (!fullvalid) {
            int rq0 = R0 + (lane >> 2);
            int ck = kt + (lane & 3) * 2;
#pragma unroll
            for (int nt = 0; nt < 2; nt++)
#pragma unroll
                for (int e = 0; e < 4; e++) {
                    int q = rq0 + ((e >= 2) ? 8 : 0);
                    int k = ck + nt * 8 + (e & 1);
                    if (k > q || k < q - (WINDOW - 1)) S[nt][e] = -1e30f;
                }
        }

        // ---- online softmax
        float tm0 = fmaxf(fmaxf(S[0][0], S[0][1]), fmaxf(S[1][0], S[1][1]));
        float tm1 = fmaxf(fmaxf(S[0][2], S[0][3]), fmaxf(S[1][2], S[1][3]));
        tm0 = fmaxf(tm0, __shfl_xor_sync(0xffffffffu, tm0, 1));
        tm0 = fmaxf(tm0, __shfl_xor_sync(0xffffffffu, tm0, 2));
        tm1 = fmaxf(tm1, __shfl_xor_sync(0xffffffffu, tm1, 1));
        tm1 = fmaxf(tm1, __shfl_xor_sync(0xffffffffu, tm1, 2));
        float mn0 = fmaxf(m0, tm0), mn1 = fmaxf(m1, tm1);
        float sc0 = __expf(m0 - mn0), sc1 = __expf(m1 - mn1);
        m0 = mn0; m1 = mn1;

        float p[2][4];
#pragma unroll
        for (int nt = 0; nt < 2; nt++) {
            p[nt][0] = __expf(S[nt][0] - mn0);
            p[nt][1] = __expf(S[nt][1] - mn0);
            p[nt][2] = __expf(S[nt][2] - mn1);
            p[nt][3] = __expf(S[nt][3] - mn1);
        }
        float rs0 = p[0][0] + p[0][1] + p[1][0] + p[1][1];
        float rs1 = p[0][2] + p[0][3] + p[1][2] + p[1][3];
        rs0 += __shfl_xor_sync(0xffffffffu, rs0, 1);
        rs0 += __shfl_xor_sync(0xffffffffu, rs0, 2);
        rs1 += __shfl_xor_sync(0xffffffffu, rs1, 1);
        rs1 += __shfl_xor_sync(0xffffffffu, rs1, 2);
        l0 = l0 * sc0 + rs0;
        l1 = l1 * sc1 + rs1;

#pragma unroll
        for (int nt = 0; nt < 16; nt++) {
            O[nt][0] *= sc0; O[nt][1] *= sc0;
            O[nt][2] *= sc1; O[nt][3] *= sc1;
        }

        // ---- P frags (hi/lo split)
        uint32_t pa[4], pal[4];
#pragma unroll
        for (int e = 0; e < 4; e++) {
            int nt = e >> 1, half = (e & 1) * 2;
            float v0 = p[nt][half], v1 = p[nt][half + 1];
            __nv_bfloat16 h0 = __float2bfloat16(v0);
            __nv_bfloat16 h1 = __float2bfloat16(v1);
            __nv_bfloat162 hh2{h0, h1};
            __nv_bfloat162 ll2{__float2bfloat16(v0 - __bfloat162float(h0)),
                               __float2bfloat16(v1 - __bfloat162float(h1))};
            pa[e] = *(uint32_t*)&hh2;
            pal[e] = *(uint32_t*)&ll2;
        }

        // ---- O += P.V (bf16x3), d-half = 128
#pragma unroll
        for (int j = 0; j < 8; j++) {
            uint32_t vb[4], vbl[4];
            int vg = dh * 16 + j * 2 + vb_gs;
            uint32_t vaddr = sKV + 16384 + vb_r * 512 + (((vg) ^ (vb_r & 7)) << 4);
            LDM4T(vb, vaddr);
            LDM4T(vbl, vaddr + 8192);
            MMA16816(O[2 * j], pa, vb[0], vb[1]);
            MMA16816(O[2 * j], pa, vbl[0], vbl[1]);
            MMA16816(O[2 * j], pal, vb[0], vb[1]);
            MMA16816(O[2 * j + 1], pa, vb[2], vb[3]);
            MMA16816(O[2 * j + 1], pa, vbl[2], vbl[3]);
            MMA16816(O[2 * j + 1], pal, vb[2], vb[3]);
        }
    }

    // ---- epilogue: normalize, split, store into Wo-GEMM A buffers
    float il0 = 1.0f / l0, il1 = 1.0f / l1;
    int row0 = Q0 + qg * 16 + (lane >> 2);
#pragma unroll
    for (int nt = 0; nt < 16; nt++) {
        int n = dh * 128 + nt * 8 + (lane & 3) * 2;
        size_t base0 = (size_t)row0 * D_MODEL + h * HD + n;
        size_t base1 = (size_t)(row0 + 8) * D_MODEL + h * HD + n;
        float v0 = O[nt][0] * il0, v1 = O[nt][1] * il0;
        float v2 = O[nt][2] * il1, v3 = O[nt][3] * il1;
        __nv_bfloat16 h0 = __float2bfloat16(v0), h1 = __float2bfloat16(v1);
        __nv_bfloat16 h2 = __float2bfloat16(v2), h3 = __float2bfloat16(v3);
        *(__nv_bfloat162*)(oh + base0) = __nv_bfloat162{h0, h1};
        *(__nv_bfloat162*)(oh + base1) = __nv_bfloat162{h2, h3};
        *(__nv_bfloat162*)(ol + base0) =
            __nv_bfloat162{__float2bfloat16(v0 - __bfloat162float(h0)),
                           __float2bfloat16(v1 - __bfloat162float(h1))};
        *(__nv_bfloat162*)(ol + base1) =
            __nv_bfloat162{__float2bfloat16(v2 - __bfloat162float(h2)),
                           __float2bfloat16(v3 - __bfloat162float(h3))};
    }
}

// ---------------------------------------------------------------------------
extern "C" void kernel_launch(void* const* d_in, const int* in_sizes, int n_in,
                              void* d_out, int out_size) {
    const float* x       = (const float*)d_in[0];
    const int* positions = (const int*)d_in[1];
    const float* Wq      = (const float*)d_in[2];
    const float* Wk      = (const float*)d_in[3];
    const float* Wv      = (const float*)d_in[4];
    const float* Wo      = (const float*)d_in[5];
    const float* q_scale = (const float*)d_in[6];
    const float* k_scale = (const float*)d_in[7];
    float* out           = (float*)d_out;

    __nv_bfloat16 *ah, *al, *wqh, *wql, *woh, *wol, *qh, *ql, *kh, *kl, *vh, *vl;
    float* qkv;
    cudaGetSymbolAddress((void**)&ah, g_ah);
    cudaGetSymbolAddress((void**)&al, g_al);
    cudaGetSymbolAddress((void**)&wqh, g_wqkv_h);
    cudaGetSymbolAddress((void**)&wql, g_wqkv_l);
    cudaGetSymbolAddress((void**)&woh, g_wo_h);
    cudaGetSymbolAddress((void**)&wol, g_wo_l);
    cudaGetSymbolAddress((void**)&qh, g_qh);
    cudaGetSymbolAddress((void**)&ql, g_ql);
    cudaGetSymbolAddress((void**)&kh, g_kh);
    cudaGetSymbolAddress((void**)&kl, g_kl);
    cudaGetSymbolAddress((void**)&vh, g_vh);
    cudaGetSymbolAddress((void**)&vl, g_vl);
    cudaGetSymbolAddress((void**)&qkv, g_qkv);

    cudaFuncSetAttribute(gemm_hmma, cudaFuncAttributeMaxDynamicSharedMemorySize,
                         GEMM_SMEM);
    cudaFuncSetAttribute(attn_tc, cudaFuncAttributeMaxDynamicSharedMemorySize,
                         ATT_SMEM);

    // weights: transpose + bf16 split
    tsplit_kernel<<<dim3(2048 / 32, 64), dim3(32, 8)>>>(Wq, wqh, wql, 2048, 0);
    tsplit_kernel<<<dim3(512 / 32, 64), dim3(32, 8)>>>(Wk, wqh, wql, 512, 2048);
    tsplit_kernel<<<dim3(512 / 32, 64), dim3(32, 8)>>>(Wv, wqh, wql, 512, 2560);
    tsplit_kernel<<<dim3(2048 / 32, 64), dim3(32, 8)>>>(Wo, woh, wol, 2048, 0);

    // activations: bf16 split
    int n4 = (L_SEQ * D_MODEL) / 4;
    split_kernel<<<(n4 + 255) / 256, 256>>>(x, ah, al, n4);

    // fused QKV projection
    gemm_hmma<<<dim3(NQKV / 128, L_SEQ / 128), 256, GEMM_SMEM>>>(
        ah, al, wqh, wql, qkv, D_MODEL, NQKV);

    // norm (+rope) + split to head-major bf16 hi/lo
    norm_split_kernel<<<dim3(L_SEQ, NH), 128>>>(qkv, 0, q_scale, 1, positions, qh, ql);
    norm_split_kernel<<<dim3(L_SEQ, NKVH), 128>>>(qkv, 2048, k_scale, 1, positions, kh, kl);
    norm_split_kernel<<<dim3(L_SEQ, NKVH), 128>>>(qkv, 2560, nullptr, 0, positions, vh, vl);

    // tensor-core attention; writes split O directly into ah/al
    attn_tc<<<dim3(L_SEQ / QB, NH), 256, ATT_SMEM>>>(qh, ql, kh, kl, vh, vl, ah, al);

    // output projection: out = O @ Wo
    gemm_hmma<<<dim3(D_MODEL / 128, L_SEQ / 128), 256, GEMM_SMEM>>>(
        ah, al, woh, wol, out, D_MODEL, D_MODEL);
}

// round 6
// speedup vs baseline: 4.6008x; 1.1596x over previous
#include <cuda_runtime.h>
#include <cuda_bf16.h>
#include <math.h>
#include <stdint.h>

#define L_SEQ 4096
#define D_MODEL 2048
#define NH 8
#define NKVH 2
#define HD 256
#define WINDOW 512
#define NQKV 3072  // 2048 q + 512 k + 512 v

// ---------------- scratch (device globals; no cudaMalloc allowed) ----------
__device__ __nv_bfloat16 g_ah[L_SEQ * D_MODEL];        // A hi (x, later attn O)
__device__ __nv_bfloat16 g_al[L_SEQ * D_MODEL];        // A lo
__device__ __nv_bfloat16 g_wqkv_h[NQKV * D_MODEL];     // [Wq|Wk|Wv]^T hi, (N,K)
__device__ __nv_bfloat16 g_wqkv_l[NQKV * D_MODEL];
__device__ __nv_bfloat16 g_wo_h[D_MODEL * D_MODEL];    // Wo^T hi
__device__ __nv_bfloat16 g_wo_l[D_MODEL * D_MODEL];
__device__ float g_qkv[L_SEQ * NQKV];                  // fused qkv activations
// head-major split q/k/v for attention
__device__ __nv_bfloat16 g_qh[NH * L_SEQ * HD];
__device__ __nv_bfloat16 g_ql[NH * L_SEQ * HD];
__device__ __nv_bfloat16 g_kh[NKVH * L_SEQ * HD];
__device__ __nv_bfloat16 g_kl[NKVH * L_SEQ * HD];
__device__ __nv_bfloat16 g_vh[NKVH * L_SEQ * HD];
__device__ __nv_bfloat16 g_vl[NKVH * L_SEQ * HD];

static __device__ __forceinline__ uint32_t smem_u32(const void* p) {
    uint32_t a;
    asm("{ .reg .u64 t; cvta.to.shared.u64 t, %1; cvt.u32.u64 %0, t; }"
        : "=r"(a) : "l"(p));
    return a;
}

#define CPA16(dst, src)                                                        \
    asm volatile("cp.async.cg.shared.global [%0], [%1], 16;"                   \
                 :: "r"(dst), "l"(src) : "memory")
#define CPA_COMMIT asm volatile("cp.async.commit_group;" ::: "memory")
#define CPA_WAIT0  asm volatile("cp.async.wait_group 0;" ::: "memory")

#define LDM4(r, addr)                                                          \
    asm volatile("ldmatrix.sync.aligned.m8n8.x4.shared.b16 {%0,%1,%2,%3}, [%4];"\
        : "=r"((r)[0]), "=r"((r)[1]), "=r"((r)[2]), "=r"((r)[3]) : "r"(addr))

#define LDM4T(r, addr)                                                         \
    asm volatile("ldmatrix.sync.aligned.m8n8.x4.trans.shared.b16 {%0,%1,%2,%3}, [%4];"\
        : "=r"((r)[0]), "=r"((r)[1]), "=r"((r)[2]), "=r"((r)[3]) : "r"(addr))

#define MMA16816(c, a, b0v, b1v)                                               \
    asm volatile("mma.sync.aligned.m16n8k16.row.col.f32.bf16.bf16.f32 "        \
        "{%0,%1,%2,%3}, {%4,%5,%6,%7}, {%8,%9}, {%0,%1,%2,%3};"                \
        : "+f"((c)[0]), "+f"((c)[1]), "+f"((c)[2]), "+f"((c)[3])               \
        : "r"((a)[0]), "r"((a)[1]), "r"((a)[2]), "r"((a)[3]),                  \
          "r"(b0v), "r"(b1v))

// ---------------- split fp32 -> bf16 hi/lo (vector x4) ---------------------
__global__ void split_kernel(const float* __restrict__ in,
                             __nv_bfloat16* __restrict__ hi,
                             __nv_bfloat16* __restrict__ lo, int n4) {
    int i = blockIdx.x * blockDim.x + threadIdx.x;
    if (i >= n4) return;
    float4 a = ((const float4*)in)[i];
    __nv_bfloat16 h0 = __float2bfloat16(a.x);
    __nv_bfloat16 h1 = __float2bfloat16(a.y);
    __nv_bfloat16 h2 = __float2bfloat16(a.z);
    __nv_bfloat16 h3 = __float2bfloat16(a.w);
    __nv_bfloat16 l0 = __float2bfloat16(a.x - __bfloat162float(h0));
    __nv_bfloat16 l1 = __float2bfloat16(a.y - __bfloat162float(h1));
    __nv_bfloat16 l2 = __float2bfloat16(a.z - __bfloat162float(h2));
    __nv_bfloat16 l3 = __float2bfloat16(a.w - __bfloat162float(h3));
    __nv_bfloat162* ph = (__nv_bfloat162*)hi;
    __nv_bfloat162* pl = (__nv_bfloat162*)lo;
    ph[i * 2]     = __nv_bfloat162{h0, h1};
    ph[i * 2 + 1] = __nv_bfloat162{h2, h3};
    pl[i * 2]     = __nv_bfloat162{l0, l1};
    pl[i * 2 + 1] = __nv_bfloat162{l2, l3};
}

// ---------------- transpose + split: W(K=2048, N) -> WT(N, 2048) hi/lo -----
__global__ void tsplit_kernel(const float* __restrict__ W,
                              __nv_bfloat16* __restrict__ th,
                              __nv_bfloat16* __restrict__ tl,
                              int N, int roff) {
    __shared__ float s[32][33];
    int n0 = blockIdx.x * 32, k0 = blockIdx.y * 32;
    int tx = threadIdx.x, ty = threadIdx.y;  // 32 x 8
#pragma unroll
    for (int r = 0; r < 4; r++)
        s[ty + r * 8][tx] = W[(size_t)(k0 + ty + r * 8) * N + n0 + tx];
    __syncthreads();
#pragma unroll
    for (int r = 0; r < 4; r++) {
        int n = n0 + ty + r * 8;
        float a = s[tx][ty + r * 8];
        __nv_bfloat16 h = __float2bfloat16(a);
        __nv_bfloat16 l = __float2bfloat16(a - __bfloat162float(h));
        th[(size_t)(roff + n) * D_MODEL + k0 + tx] = h;
        tl[(size_t)(roff + n) * D_MODEL + k0 + tx] = l;
    }
}

// ---------------- HMMA bf16x3 GEMM: C[M,N] = A @ B^T ------------------------
// 2 CTAs/SM: B-frags loaded once per ks, A-frags streamed (regs < 128).
#define OPSTRIDE 80
#define OP_TILE_B (128 * OPSTRIDE)
#define BUF_BYTES (4 * OP_TILE_B)
#define GEMM_SMEM (2 * BUF_BYTES)

__global__ void __launch_bounds__(256, 2)
gemm_hmma(const __nv_bfloat16* __restrict__ Ah, const __nv_bfloat16* __restrict__ Al,
          const __nv_bfloat16* __restrict__ Bh, const __nv_bfloat16* __restrict__ Bl,
          float* __restrict__ C, int K, int ldc) {
    extern __shared__ __align__(128) char gsm[];
    const int tid = threadIdx.x;
    const int lane = tid & 31;
    const int wid = tid >> 5;
    const int wm = (wid & 1) * 64;
    const int wn = (wid >> 1) * 32;
    const int bm = blockIdx.y * 128;
    const int bn = blockIdx.x * 128;
    const uint32_t sbase = smem_u32(gsm);

    const __nv_bfloat16* gptr[4] = {
        Ah + (size_t)bm * K, Al + (size_t)bm * K,
        Bh + (size_t)bn * K, Bl + (size_t)bn * K };

    float acc[4][4][4];
#pragma unroll
    for (int a = 0; a < 4; a++)
#pragma unroll
        for (int b = 0; b < 4; b++)
#pragma unroll
            for (int c = 0; c < 4; c++) acc[a][b][c] = 0.f;

    const uint32_t a_off = (uint32_t)(lane & 15) * OPSTRIDE + ((lane & 16) ? 16u : 0u);
    const uint32_t b_off = (uint32_t)(((lane & 16) ? 8 : 0) + (lane & 7)) * OPSTRIDE
                         + ((lane & 8) ? 16u : 0u);

    const int nch = K >> 5;
    {
        uint32_t dbase = sbase;
#pragma unroll
        for (int it = 0; it < 8; it++) {
            int s = it * 256 + tid;
            int op = s >> 9, t = s & 511;
            int row = t >> 2, cc = t & 3;
            const __nv_bfloat16* src = gptr[op] + (size_t)row * K + cc * 8;
            uint32_t dst = dbase + op * OP_TILE_B + row * OPSTRIDE + cc * 16;
            CPA16(dst, src);
        }
        CPA_COMMIT;
    }

    for (int c = 0; c < nch; c++) {
        if (c + 1 < nch) {
            const int k0 = (c + 1) << 5;
            uint32_t dbase = sbase + (((c + 1) & 1) ? BUF_BYTES : 0);
#pragma unroll
            for (int it = 0; it < 8; it++) {
                int s = it * 256 + tid;
                int op = s >> 9, t = s & 511;
                int row = t >> 2, cc = t & 3;
                const __nv_bfloat16* src = gptr[op] + (size_t)row * K + k0 + cc * 8;
                uint32_t dst = dbase + op * OP_TILE_B + row * OPSTRIDE + cc * 16;
                CPA16(dst, src);
            }
            CPA_COMMIT;
            asm volatile("cp.async.wait_group 1;" ::: "memory");
        } else {
            CPA_WAIT0;
        }
        __syncthreads();

        const uint32_t dbase = sbase + ((c & 1) ? BUF_BYTES : 0);
#pragma unroll
        for (int ks = 0; ks < 2; ks++) {
            const uint32_t kb = ks * 32;
            uint32_t bhf[2][4], blf[2][4];
#pragma unroll
            for (int np = 0; np < 2; np++) {
                uint32_t rb = (wn + np * 16) * OPSTRIDE + kb + b_off;
                LDM4(bhf[np], dbase + 2 * OP_TILE_B + rb);
                LDM4(blf[np], dbase + 3 * OP_TILE_B + rb);
            }
#pragma unroll
            for (int mt = 0; mt < 4; mt++) {
                uint32_t ahf[4], alf[4];
                uint32_t ra = (wm + mt * 16) * OPSTRIDE + kb + a_off;
                LDM4(ahf, dbase + ra);
                LDM4(alf, dbase + OP_TILE_B + ra);
#pragma unroll
                for (int nt = 0; nt < 4; nt++) {
                    const int np = nt >> 1, sel = (nt & 1) * 2;
                    MMA16816(acc[mt][nt], ahf, bhf[np][sel], bhf[np][sel + 1]);
                    MMA16816(acc[mt][nt], ahf, blf[np][sel], blf[np][sel + 1]);
                    MMA16816(acc[mt][nt], alf, bhf[np][sel], bhf[np][sel + 1]);
                }
            }
        }
        __syncthreads();
    }

#pragma unroll
    for (int mt = 0; mt < 4; mt++) {
        int r0 = bm + wm + mt * 16 + (lane >> 2);
#pragma unroll
        for (int nt = 0; nt < 4; nt++) {
            int c0 = bn + wn + nt * 8 + (lane & 3) * 2;
            *(float2*)(C + (size_t)r0 * ldc + c0) =
                make_float2(acc[mt][nt][0], acc[mt][nt][1]);
            *(float2*)(C + (size_t)(r0 + 8) * ldc + c0) =
                make_float2(acc[mt][nt][2], acc[mt][nt][3]);
        }
    }
}

// ---------------- fused RMS norm (+scale, +RoPE) -> split bf16 head-major --
// grid.y: 0..7 = q heads, 8..9 = k heads, 10..11 = v heads
__global__ void norm_split_all(const float* __restrict__ qkv,
                               const float* __restrict__ q_scale,
                               const float* __restrict__ k_scale,
                               const int* __restrict__ positions,
                               __nv_bfloat16* __restrict__ qh, __nv_bfloat16* __restrict__ ql,
                               __nv_bfloat16* __restrict__ kh, __nv_bfloat16* __restrict__ kl,
                               __nv_bfloat16* __restrict__ vh, __nv_bfloat16* __restrict__ vl) {
    const int l = blockIdx.x;
    const int slot = blockIdx.y;   // 0..11
    int headoff, hh, do_rope;
    const float* scale;
    __nv_bfloat16 *oh, *ol;
    if (slot < 8)       { headoff = 0;    hh = slot;      scale = q_scale; do_rope = 1; oh = qh; ol = ql; }
    else if (slot < 10) { headoff = 2048; hh = slot - 8;  scale = k_scale; do_rope = 1; oh = kh; ol = kl; }
    else                { headoff = 2560; hh = slot - 10; scale = nullptr; do_rope = 0; oh = vh; ol = vl; }

    const float* p = qkv + (size_t)l * NQKV + headoff + hh * HD;
    const int t = threadIdx.x;  // 0..127
    const int lane = t & 31;
    const int wid = t >> 5;

    float a = p[t];
    float b = p[t + 128];
    float ss = a * a + b * b;
#pragma unroll
    for (int off = 16; off > 0; off >>= 1)
        ss += __shfl_xor_sync(0xffffffffu, ss, off);
    __shared__ float red[4];
    if (lane == 0) red[wid] = ss;
    __syncthreads();
    float total = red[0] + red[1] + red[2] + red[3];
    float inv = rsqrtf(total * (1.0f / HD) + 1e-6f);

    float xa = a * inv, xb = b * inv;
    if (scale) { xa *= scale[t]; xb *= scale[t + 128]; }

    float ya, yb;
    if (do_rope) {
        float pos = (float)positions[l];
        float ts = powf(10000.0f, 2.0f * (float)t / (float)HD);
        float ang = pos / ts;
        float sn = sinf(ang), cs = cosf(ang);
        ya = xa * cs - xb * sn;
        yb = xb * cs + xa * sn;
    } else {
        ya = xa; yb = xb;
    }
    size_t o = ((size_t)hh * L_SEQ + l) * HD;
    __nv_bfloat16 ha = __float2bfloat16(ya);
    __nv_bfloat16 hb = __float2bfloat16(yb);
    oh[o + t]       = ha;
    oh[o + t + 128] = hb;
    ol[o + t]       = __float2bfloat16(ya - __bfloat162float(ha));
    ol[o + t + 128] = __float2bfloat16(yb - __bfloat162float(hb));
}

// ---------------- tensor-core sliding-window flash attention ---------------
#define QB 64
#define KT 16
#define ATT_SMEM (96 * 1024)

__global__ void __launch_bounds__(256, 2)
attn_tc(const __nv_bfloat16* __restrict__ qhp, const __nv_bfloat16* __restrict__ qlp,
        const __nv_bfloat16* __restrict__ khp, const __nv_bfloat16* __restrict__ klp,
        const __nv_bfloat16* __restrict__ vhp, const __nv_bfloat16* __restrict__ vlp,
        __nv_bfloat16* __restrict__ oh, __nv_bfloat16* __restrict__ ol) {
    extern __shared__ __align__(128) char asmem[];
    const int tid = threadIdx.x, lane = tid & 31, wid = tid >> 5;
    const int qb = blockIdx.x, h = blockIdx.y;
    const int kvh = h / (NH / NKVH);
    const int Q0 = qb * QB;
    const int qg = wid >> 1;   // 0..3
    const int dh = wid & 1;    // d half
    const uint32_t sb = smem_u32(asmem);
    const uint32_t sQ = sb;                 // hi; lo at +32768
    const uint32_t sKV = sb + 65536;        // Kh | Kl(+8192) | Vh(+16384) | Vl(+24576)

    // ---- stage Q (64 rows x 256d, hi+lo) with xor swizzle
#pragma unroll
    for (int i = 0; i < 16; i++) {
        int gid = i * 256 + tid;
        int mat = gid >> 11;           // 0=hi 1=lo
        int t = gid & 2047;
        int row = t >> 5, g = t & 31;
        const __nv_bfloat16* src = (mat ? qlp : qhp)
            + ((size_t)h * L_SEQ + Q0 + row) * HD + g * 8;
        uint32_t dst = sQ + mat * 32768 + row * 512 + ((g ^ (row & 7)) << 4);
        CPA16(dst, src);
    }
    CPA_COMMIT;

    float m0 = -1e9f, m1 = -1e9f;
    float l0 = 0.f, l1 = 0.f;
    float O[16][4];
#pragma unroll
    for (int nt = 0; nt < 16; nt++)
#pragma unroll
        for (int e = 0; e < 4; e++) O[nt][e] = 0.f;

    int kstart = Q0 - (WINDOW - 1);
    if (kstart < 0) kstart = 0;
    kstart &= ~(KT - 1);
    const int kend = Q0 + QB;
    const int R0 = Q0 + qg * 16;

    const int qa_r = ((lane >> 3) & 1) * 8 + (lane & 7);
    const int qa_gs = (lane >> 4);
    const int kb_r = ((lane >> 4) & 1) * 8 + (lane & 7);
    const int kb_gs = ((lane >> 3) & 1);
    const int vb_r = ((lane >> 3) & 1) * 8 + (lane & 7);
    const int vb_gs = (lane >> 4);

    CPA_WAIT0;
    __syncthreads();

    for (int kt = kstart; kt < kend; kt += KT) {
        __syncthreads();
#pragma unroll
        for (int i = 0; i < 8; i++) {
            int gid = i * 256 + tid;
            int mat = gid >> 9;
            int t = gid & 511;
            int row = t >> 5, g = t & 31;
            const __nv_bfloat16* srcb =
                (mat == 0) ? khp : (mat == 1) ? klp : (mat == 2) ? vhp : vlp;
            const __nv_bfloat16* src = srcb
                + ((size_t)kvh * L_SEQ + kt + row) * HD + g * 8;
            uint32_t dst = sKV + mat * 8192 + row * 512 + ((g ^ (row & 7)) << 4);
            CPA16(dst, src);
        }
        CPA_COMMIT;
        CPA_WAIT0;
        __syncthreads();

        float S[2][4];
#pragma unroll
        for (int nt = 0; nt < 2; nt++)
#pragma unroll
            for (int e = 0; e < 4; e++) S[nt][e] = 0.f;

#pragma unroll
        for (int ks = 0; ks < 16; ks++) {
            uint32_t qa[4], qal[4], kb[4], kbl[4];
            int qrow = qg * 16 + qa_r;
            int qg_g = ks * 2 + qa_gs;
            uint32_t qaddr = sQ + qrow * 512 + (((qg_g) ^ (qrow & 7)) << 4);
            LDM4(qa, qaddr);
            LDM4(qal, qaddr + 32768);
            int kg_g = ks * 2 + kb_gs;
            uint32_t kaddr = sKV + kb_r * 512 + (((kg_g) ^ (kb_r & 7)) << 4);
            LDM4(kb, kaddr);
            LDM4(kbl, kaddr + 8192);
            MMA16816(S[0], qa, kb[0], kb[1]);
            MMA16816(S[0], qa, kbl[0], kbl[1]);
            MMA16816(S[0], qal, kb[0], kb[1]);
            MMA16816(S[1], qa, kb[2], kb[3]);
            MMA16816(S[1], qa, kbl[2], kbl[3]);
            MMA16816(S[1], qal, kb[2], kb[3]);
        }

        const bool fullvalid = (kt + KT - 1 <= R0) && (kt >= R0 + 15 - (WINDOW - 1));
        if (!fullvalid) {
            int rq0 = R0 + (lane >> 2);
            int ck = kt + (lane & 3) * 2;
#pragma unroll
            for (int nt = 0; nt < 2; nt++)
#pragma unroll
                for (int e = 0; e < 4; e++) {
                    int q = rq0 + ((e >= 2) ? 8 : 0);
                    int k = ck + nt * 8 + (e & 1);
                    if (k > q || k < q - (WINDOW - 1)) S[nt][e] = -1e30f;
                }
        }

        float tm0 = fmaxf(fmaxf(S[0][0], S[0][1]), fmaxf(S[1][0], S[1][1]));
        float tm1 = fmaxf(fmaxf(S[0][2], S[0][3]), fmaxf(S[1][2], S[1][3]));
        tm0 = fmaxf(tm0, __shfl_xor_sync(0xffffffffu, tm0, 1));
        tm0 = fmaxf(tm0, __shfl_xor_sync(0xffffffffu, tm0, 2));
        tm1 = fmaxf(tm1, __shfl_xor_sync(0xffffffffu, tm1, 1));
        tm1 = fmaxf(tm1, __shfl_xor_sync(0xffffffffu, tm1, 2));
        float mn0 = fmaxf(m0, tm0), mn1 = fmaxf(m1, tm1);
        float sc0 = __expf(m0 - mn0), sc1 = __expf(m1 - mn1);
        m0 = mn0; m1 = mn1;

        float p[2][4];
#pragma unroll
        for (int nt = 0; nt < 2; nt++) {
            p[nt][0] = __expf(S[nt][0] - mn0);
            p[nt][1] = __expf(S[nt][1] - mn0);
            p[nt][2] = __expf(S[nt][2] - mn1);
            p[nt][3] = __expf(S[nt][3] - mn1);
        }
        float rs0 = p[0][0] + p[0][1] + p[1][0] + p[1][1];
        float rs1 = p[0][2] + p[0][3] + p[1][2] + p[1][3];
        rs0 += __shfl_xor_sync(0xffffffffu, rs0, 1);
        rs0 += __shfl_xor_sync(0xffffffffu, rs0, 2);
        rs1 += __shfl_xor_sync(0xffffffffu, rs1, 1);
        rs1 += __shfl_xor_sync(0xffffffffu, rs1, 2);
        l0 = l0 * sc0 + rs0;
        l1 = l1 * sc1 + rs1;

#pragma unroll
        for (int nt = 0; nt < 16; nt++) {
            O[nt][0] *= sc0; O[nt][1] *= sc0;
            O[nt][2] *= sc1; O[nt][3] *= sc1;
        }

        uint32_t pa[4], pal[4];
#pragma unroll
        for (int e = 0; e < 4; e++) {
            int nt = e >> 1, half = (e & 1) * 2;
            float v0 = p[nt][half], v1 = p[nt][half + 1];
            __nv_bfloat16 h0 = __float2bfloat16(v0);
            __nv_bfloat16 h1 = __float2bfloat16(v1);
            __nv_bfloat162 hh2{h0, h1};
            __nv_bfloat162 ll2{__float2bfloat16(v0 - __bfloat162float(h0)),
                               __float2bfloat16(v1 - __bfloat162float(h1))};
            pa[e] = *(uint32_t*)&hh2;
            pal[e] = *(uint32_t*)&ll2;
        }

#pragma unroll
        for (int j = 0; j < 8; j++) {
            uint32_t vb[4], vbl[4];
            int vg = dh * 16 + j * 2 + vb_gs;
            uint32_t vaddr = sKV + 16384 + vb_r * 512 + (((vg) ^ (vb_r & 7)) << 4);
            LDM4T(vb, vaddr);
            LDM4T(vbl, vaddr + 8192);
            MMA16816(O[2 * j], pa, vb[0], vb[1]);
            MMA16816(O[2 * j], pa, vbl[0], vbl[1]);
            MMA16816(O[2 * j], pal, vb[0], vb[1]);
            MMA16816(O[2 * j + 1], pa, vb[2], vb[3]);
            MMA16816(O[2 * j + 1], pa, vbl[2], vbl[3]);
            MMA16816(O[2 * j + 1], pal, vb[2], vb[3]);
        }
    }

    float il0 = 1.0f / l0, il1 = 1.0f / l1;
    int row0 = Q0 + qg * 16 + (lane >> 2);
#pragma unroll
    for (int nt = 0; nt < 16; nt++) {
        int n = dh * 128 + nt * 8 + (lane & 3) * 2;
        size_t base0 = (size_t)row0 * D_MODEL + h * HD + n;
        size_t base1 = (size_t)(row0 + 8) * D_MODEL + h * HD + n;
        float v0 = O[nt][0] * il0, v1 = O[nt][1] * il0;
        float v2 = O[nt][2] * il1, v3 = O[nt][3] * il1;
        __nv_bfloat16 h0 = __float2bfloat16(v0), h1 = __float2bfloat16(v1);
        __nv_bfloat16 h2 = __float2bfloat16(v2), h3 = __float2bfloat16(v3);
        *(__nv_bfloat162*)(oh + base0) = __nv_bfloat162{h0, h1};
        *(__nv_bfloat162*)(oh + base1) = __nv_bfloat162{h2, h3};
        *(__nv_bfloat162*)(ol + base0) =
            __nv_bfloat162{__float2bfloat16(v0 - __bfloat162float(h0)),
                           __float2bfloat16(v1 - __bfloat162float(h1))};
        *(__nv_bfloat162*)(ol + base1) =
            __nv_bfloat162{__float2bfloat16(v2 - __bfloat162float(h2)),
                           __float2bfloat16(v3 - __bfloat162float(h3))};
    }
}

// ---------------------------------------------------------------------------
extern "C" void kernel_launch(void* const* d_in, const int* in_sizes, int n_in,
                              void* d_out, int out_size) {
    const float* x       = (const float*)d_in[0];
    const int* positions = (const int*)d_in[1];
    const float* Wq      = (const float*)d_in[2];
    const float* Wk      = (const float*)d_in[3];
    const float* Wv      = (const float*)d_in[4];
    const float* Wo      = (const float*)d_in[5];
    const float* q_scale = (const float*)d_in[6];
    const float* k_scale = (const float*)d_in[7];
    float* out           = (float*)d_out;

    __nv_bfloat16 *ah, *al, *wqh, *wql, *woh, *wol, *qh, *ql, *kh, *kl, *vh, *vl;
    float* qkv;
    cudaGetSymbolAddress((void**)&ah, g_ah);
    cudaGetSymbolAddress((void**)&al, g_al);
    cudaGetSymbolAddress((void**)&wqh, g_wqkv_h);
    cudaGetSymbolAddress((void**)&wql, g_wqkv_l);
    cudaGetSymbolAddress((void**)&woh, g_wo_h);
    cudaGetSymbolAddress((void**)&wol, g_wo_l);
    cudaGetSymbolAddress((void**)&qh, g_qh);
    cudaGetSymbolAddress((void**)&ql, g_ql);
    cudaGetSymbolAddress((void**)&kh, g_kh);
    cudaGetSymbolAddress((void**)&kl, g_kl);
    cudaGetSymbolAddress((void**)&vh, g_vh);
    cudaGetSymbolAddress((void**)&vl, g_vl);
    cudaGetSymbolAddress((void**)&qkv, g_qkv);

    cudaFuncSetAttribute(gemm_hmma, cudaFuncAttributeMaxDynamicSharedMemorySize,
                         GEMM_SMEM);
    cudaFuncSetAttribute(attn_tc, cudaFuncAttributeMaxDynamicSharedMemorySize,
                         ATT_SMEM);

    // weights: transpose + bf16 split
    tsplit_kernel<<<dim3(2048 / 32, 64), dim3(32, 8)>>>(Wq, wqh, wql, 2048, 0);
    tsplit_kernel<<<dim3(512 / 32, 64), dim3(32, 8)>>>(Wk, wqh, wql, 512, 2048);
    tsplit_kernel<<<dim3(512 / 32, 64), dim3(32, 8)>>>(Wv, wqh, wql, 512, 2560);
    tsplit_kernel<<<dim3(2048 / 32, 64), dim3(32, 8)>>>(Wo, woh, wol, 2048, 0);

    // activations: bf16 split
    int n4 = (L_SEQ * D_MODEL) / 4;
    split_kernel<<<(n4 + 255) / 256, 256>>>(x, ah, al, n4);

    // fused QKV projection
    gemm_hmma<<<dim3(NQKV / 128, L_SEQ / 128), 256, GEMM_SMEM>>>(
        ah, al, wqh, wql, qkv, D_MODEL, NQKV);

    // fused norm (+rope) + split, all of q/k/v in one launch
    norm_split_all<<<dim3(L_SEQ, 12), 128>>>(qkv, q_scale, k_scale, positions,
                                             qh, ql, kh, kl, vh, vl);

    // tensor-core attention; writes split O directly into ah/al
    attn_tc<<<dim3(L_SEQ / QB, NH), 256, ATT_SMEM>>>(qh, ql, kh, kl, vh, vl, ah, al);

    // output projection: out = O @ Wo
    gemm_hmma<<<dim3(D_MODEL / 128, L_SEQ / 128), 256, GEMM_SMEM>>>(
        ah, al, woh, wol, out, D_MODEL, D_MODEL);
}

// round 9
// speedup vs baseline: 5.1061x; 1.1098x over previous
#include <cuda_runtime.h>
#include <cuda_bf16.h>
#include <math.h>
#include <stdint.h>

#define L_SEQ 4096
#define D_MODEL 2048
#define NH 8
#define NKVH 2
#define HD 256
#define WINDOW 512
#define NQKV 3072  // 2048 q + 512 k + 512 v

// ---------------- scratch (device globals; no cudaMalloc allowed) ----------
__device__ __nv_bfloat16 g_ah[L_SEQ * D_MODEL];        // A hi (x, later attn O)
__device__ __nv_bfloat16 g_al[L_SEQ * D_MODEL];        // A lo
__device__ __nv_bfloat16 g_wqkv_h[NQKV * D_MODEL];     // [Wq|Wk|Wv]^T hi, (N,K)
__device__ __nv_bfloat16 g_wqkv_l[NQKV * D_MODEL];
__device__ __nv_bfloat16 g_wo_h[D_MODEL * D_MODEL];    // Wo^T hi
__device__ __nv_bfloat16 g_wo_l[D_MODEL * D_MODEL];
__device__ float g_qkv[L_SEQ * NQKV];                  // fused qkv activations
// head-major split q/k/v for attention
__device__ __nv_bfloat16 g_qh[NH * L_SEQ * HD];
__device__ __nv_bfloat16 g_ql[NH * L_SEQ * HD];
__device__ __nv_bfloat16 g_kh[NKVH * L_SEQ * HD];
__device__ __nv_bfloat16 g_kl[NKVH * L_SEQ * HD];
__device__ __nv_bfloat16 g_vh[NKVH * L_SEQ * HD];
__device__ __nv_bfloat16 g_vl[NKVH * L_SEQ * HD];

static __device__ __forceinline__ uint32_t smem_u32(const void* p) {
    uint32_t a;
    asm("{ .reg .u64 t; cvta.to.shared.u64 t, %1; cvt.u32.u64 %0, t; }"
        : "=r"(a) : "l"(p));
    return a;
}

#define CPA16(dst, src)                                                        \
    asm volatile("cp.async.cg.shared.global [%0], [%1], 16;"                   \
                 :: "r"(dst), "l"(src) : "memory")
#define CPA_COMMIT asm volatile("cp.async.commit_group;" ::: "memory")
#define CPA_WAIT0  asm volatile("cp.async.wait_group 0;" ::: "memory")
#define CPA_WAIT1  asm volatile("cp.async.wait_group 1;" ::: "memory")

#define LDM4(r, addr)                                                          \
    asm volatile("ldmatrix.sync.aligned.m8n8.x4.shared.b16 {%0,%1,%2,%3}, [%4];"\
        : "=r"((r)[0]), "=r"((r)[1]), "=r"((r)[2]), "=r"((r)[3]) : "r"(addr))

#define LDM4T(r, addr)                                                         \
    asm volatile("ldmatrix.sync.aligned.m8n8.x4.trans.shared.b16 {%0,%1,%2,%3}, [%4];"\
        : "=r"((r)[0]), "=r"((r)[1]), "=r"((r)[2]), "=r"((r)[3]) : "r"(addr))

#define MMA16816(c, a, b0v, b1v)                                               \
    asm volatile("mma.sync.aligned.m16n8k16.row.col.f32.bf16.bf16.f32 "        \
        "{%0,%1,%2,%3}, {%4,%5,%6,%7}, {%8,%9}, {%0,%1,%2,%3};"                \
        : "+f"((c)[0]), "+f"((c)[1]), "+f"((c)[2]), "+f"((c)[3])               \
        : "r"((a)[0]), "r"((a)[1]), "r"((a)[2]), "r"((a)[3]),                  \
          "r"(b0v), "r"(b1v))

// ---------------- split fp32 -> bf16 hi/lo (vector x4) ---------------------
__global__ void split_kernel(const float* __restrict__ in,
                             __nv_bfloat16* __restrict__ hi,
                             __nv_bfloat16* __restrict__ lo, int n4) {
    int i = blockIdx.x * blockDim.x + threadIdx.x;
    if (i >= n4) return;
    float4 a = ((const float4*)in)[i];
    __nv_bfloat16 h0 = __float2bfloat16(a.x);
    __nv_bfloat16 h1 = __float2bfloat16(a.y);
    __nv_bfloat16 h2 = __float2bfloat16(a.z);
    __nv_bfloat16 h3 = __float2bfloat16(a.w);
    __nv_bfloat16 l0 = __float2bfloat16(a.x - __bfloat162float(h0));
    __nv_bfloat16 l1 = __float2bfloat16(a.y - __bfloat162float(h1));
    __nv_bfloat16 l2 = __float2bfloat16(a.z - __bfloat162float(h2));
    __nv_bfloat16 l3 = __float2bfloat16(a.w - __bfloat162float(h3));
    __nv_bfloat162* ph = (__nv_bfloat162*)hi;
    __nv_bfloat162* pl = (__nv_bfloat162*)lo;
    ph[i * 2]     = __nv_bfloat162{h0, h1};
    ph[i * 2 + 1] = __nv_bfloat162{h2, h3};
    pl[i * 2]     = __nv_bfloat162{l0, l1};
    pl[i * 2 + 1] = __nv_bfloat162{l2, l3};
}

// ---------------- transpose + split: W(K=2048, N) -> WT(N, 2048) hi/lo -----
__global__ void tsplit_kernel(const float* __restrict__ W,
                              __nv_bfloat16* __restrict__ th,
                              __nv_bfloat16* __restrict__ tl,
                              int N, int roff) {
    __shared__ float s[32][33];
    int n0 = blockIdx.x * 32, k0 = blockIdx.y * 32;
    int tx = threadIdx.x, ty = threadIdx.y;  // 32 x 8
#pragma unroll
    for (int r = 0; r < 4; r++)
        s[ty + r * 8][tx] = W[(size_t)(k0 + ty + r * 8) * N + n0 + tx];
    __syncthreads();
#pragma unroll
    for (int r = 0; r < 4; r++) {
        int n = n0 + ty + r * 8;
        float a = s[tx][ty + r * 8];
        __nv_bfloat16 h = __float2bfloat16(a);
        __nv_bfloat16 l = __float2bfloat16(a - __bfloat162float(h));
        th[(size_t)(roff + n) * D_MODEL + k0 + tx] = h;
        tl[(size_t)(roff + n) * D_MODEL + k0 + tx] = l;
    }
}

// ---------------- HMMA bf16x3 GEMM: C[M,N] = A @ B^T ------------------------
// 64B-stride XOR-swizzled smem (no padding), 3-stage cp.async, 2 CTAs/SM,
// one __syncthreads per K-chunk.
#define GOP_B 8192          // per-operand tile: 128 rows x 64B
#define GBUF_B (4 * GOP_B)  // Ah, Al, Bh, Bl = 32KB
#define GEMM_SMEM (3 * GBUF_B)  // 96KB

// swizzled offset within an operand tile: row in [0,128), granule g in [0,4)
#define GSW(row, g) (((row) << 6) + ((((g) ^ (((row) >> 1) & 3)) << 4)))

__global__ void __launch_bounds__(256, 2)
gemm_hmma(const __nv_bfloat16* __restrict__ Ah, const __nv_bfloat16* __restrict__ Al,
          const __nv_bfloat16* __restrict__ Bh, const __nv_bfloat16* __restrict__ Bl,
          float* __restrict__ C, int K, int ldc) {
    extern __shared__ __align__(128) char gsm[];
    const int tid = threadIdx.x;
    const int lane = tid & 31;
    const int wid = tid >> 5;
    const int wm = (wid & 1) * 64;
    const int wn = (wid >> 1) * 32;
    const int bm = blockIdx.y * 128;
    const int bn = blockIdx.x * 128;
    const uint32_t sbase = smem_u32(gsm);

    const __nv_bfloat16* gptr[4] = {
        Ah + (size_t)bm * K, Al + (size_t)bm * K,
        Bh + (size_t)bn * K, Bl + (size_t)bn * K };

    float acc[4][4][4];
#pragma unroll
    for (int a = 0; a < 4; a++)
#pragma unroll
        for (int b = 0; b < 4; b++)
#pragma unroll
            for (int c = 0; c < 4; c++) acc[a][b][c] = 0.f;

    // per-lane fragment addressing pieces
    const int a_row_l = lane & 15;
    const int a_gs = lane >> 4;
    const int b_row_l = ((lane & 16) ? 8 : 0) + (lane & 7);
    const int b_gs = (lane >> 3) & 1;

    const int nch = K >> 5;

    // stage chunk `c` into buffer c%3 (8 x 16B per thread)
    auto stage = [&](int c) {
        const int k0 = c << 5;
        const uint32_t dbase = sbase + (uint32_t)(c % 3) * GBUF_B;
#pragma unroll
        for (int it = 0; it < 8; it++) {
            int s = it * 256 + tid;
            int op = s >> 9, t = s & 511;
            int row = t >> 2, cc = t & 3;
            const __nv_bfloat16* src = gptr[op] + (size_t)row * K + k0 + cc * 8;
            uint32_t dst = dbase + op * GOP_B + GSW(row, cc);
            CPA16(dst, src);
        }
        CPA_COMMIT;
    };

    stage(0);
    if (nch > 1) stage(1);

    for (int c = 0; c < nch; c++) {
        if (c + 1 < nch) { CPA_WAIT1; } else { CPA_WAIT0; }
        __syncthreads();
        if (c + 2 < nch) stage(c + 2);

        const uint32_t dbase = sbase + (uint32_t)(c % 3) * GBUF_B;
#pragma unroll
        for (int ks = 0; ks < 2; ks++) {
            const int kb2 = ks * 2;
            uint32_t bhf[2][4], blf[2][4];
#pragma unroll
            for (int np = 0; np < 2; np++) {
                int rb = wn + np * 16 + b_row_l;
                uint32_t offb = GSW(rb, kb2 + b_gs);
                LDM4(bhf[np], dbase + 2 * GOP_B + offb);
                LDM4(blf[np], dbase + 3 * GOP_B + offb);
            }
#pragma unroll
            for (int mt = 0; mt < 4; mt++) {
                uint32_t ahf[4], alf[4];
                int ra = wm + mt * 16 + a_row_l;
                uint32_t offa = GSW(ra, kb2 + a_gs);
                LDM4(ahf, dbase + offa);
                LDM4(alf, dbase + GOP_B + offa);
#pragma unroll
                for (int nt = 0; nt < 4; nt++) {
                    const int np = nt >> 1, sel = (nt & 1) * 2;
                    MMA16816(acc[mt][nt], ahf, bhf[np][sel], bhf[np][sel + 1]);
                    MMA16816(acc[mt][nt], ahf, blf[np][sel], blf[np][sel + 1]);
                    MMA16816(acc[mt][nt], alf, bhf[np][sel], bhf[np][sel + 1]);
                }
            }
        }
    }

#pragma unroll
    for (int mt = 0; mt < 4; mt++) {
        int r0 = bm + wm + mt * 16 + (lane >> 2);
#pragma unroll
        for (int nt = 0; nt < 4; nt++) {
            int c0 = bn + wn + nt * 8 + (lane & 3) * 2;
            *(float2*)(C + (size_t)r0 * ldc + c0) =
                make_float2(acc[mt][nt][0], acc[mt][nt][1]);
            *(float2*)(C + (size_t)(r0 + 8) * ldc + c0) =
                make_float2(acc[mt][nt][2], acc[mt][nt][3]);
        }
    }
}

// ---------------- fused RMS norm (+scale, +RoPE) -> split bf16 head-major --
// grid.y: 0..7 = q heads, 8..9 = k heads, 10..11 = v heads
__global__ void norm_split_all(const float* __restrict__ qkv,
                               const float* __restrict__ q_scale,
                               const float* __restrict__ k_scale,
                               const int* __restrict__ positions,
                               __nv_bfloat16* __restrict__ qh, __nv_bfloat16* __restrict__ ql,
                               __nv_bfloat16* __restrict__ kh, __nv_bfloat16* __restrict__ kl,
                               __nv_bfloat16* __restrict__ vh, __nv_bfloat16* __restrict__ vl) {
    const int l = blockIdx.x;
    const int slot = blockIdx.y;   // 0..11
    int headoff, hh, do_rope;
    const float* scale;
    __nv_bfloat16 *oh, *ol;
    if (slot < 8)       { headoff = 0;    hh = slot;      scale = q_scale; do_rope = 1; oh = qh; ol = ql; }
    else if (slot < 10) { headoff = 2048; hh = slot - 8;  scale = k_scale; do_rope = 1; oh = kh; ol = kl; }
    else                { headoff = 2560; hh = slot - 10; scale = nullptr; do_rope = 0; oh = vh; ol = vl; }

    const float* p = qkv + (size_t)l * NQKV + headoff + hh * HD;
    const int t = threadIdx.x;  // 0..127
    const int lane = t & 31;
    const int wid = t >> 5;

    float a = p[t];
    float b = p[t + 128];
    float ss = a * a + b * b;
#pragma unroll
    for (int off = 16; off > 0; off >>= 1)
        ss += __shfl_xor_sync(0xffffffffu, ss, off);
    __shared__ float red[4];
    if (lane == 0) red[wid] = ss;
    __syncthreads();
    float total = red[0] + red[1] + red[2] + red[3];
    float inv = rsqrtf(total * (1.0f / HD) + 1e-6f);

    float xa = a * inv, xb = b * inv;
    if (scale) { xa *= scale[t]; xb *= scale[t + 128]; }

    float ya, yb;
    if (do_rope) {
        float pos = (float)positions[l];
        float ts = powf(10000.0f, 2.0f * (float)t / (float)HD);
        float ang = pos / ts;
        float sn = sinf(ang), cs = cosf(ang);
        ya = xa * cs - xb * sn;
        yb = xb * cs + xa * sn;
    } else {
        ya = xa; yb = xb;
    }
    size_t o = ((size_t)hh * L_SEQ + l) * HD;
    __nv_bfloat16 ha = __float2bfloat16(ya);
    __nv_bfloat16 hb = __float2bfloat16(yb);
    oh[o + t]       = ha;
    oh[o + t + 128] = hb;
    ol[o + t]       = __float2bfloat16(ya - __bfloat162float(ha));
    ol[o + t + 128] = __float2bfloat16(yb - __bfloat162float(hb));
}

// ---------------- tensor-core sliding-window flash attention ---------------
#define QB 64
#define KT 16
#define ATT_SMEM (96 * 1024)

__global__ void __launch_bounds__(256, 2)
attn_tc(const __nv_bfloat16* __restrict__ qhp, const __nv_bfloat16* __restrict__ qlp,
        const __nv_bfloat16* __restrict__ khp, const __nv_bfloat16* __restrict__ klp,
        const __nv_bfloat16* __restrict__ vhp, const __nv_bfloat16* __restrict__ vlp,
        __nv_bfloat16* __restrict__ oh, __nv_bfloat16* __restrict__ ol) {
    extern __shared__ __align__(128) char asmem[];
    const int tid = threadIdx.x, lane = tid & 31, wid = tid >> 5;
    const int qb = blockIdx.x, h = blockIdx.y;
    const int kvh = h / (NH / NKVH);
    const int Q0 = qb * QB;
    const int qg = wid >> 1;   // 0..3
    const int dh = wid & 1;    // d half
    const uint32_t sb = smem_u32(asmem);
    const uint32_t sQ = sb;                 // hi; lo at +32768
    const uint32_t sKV = sb + 65536;        // Kh | Kl(+8192) | Vh(+16384) | Vl(+24576)

    // ---- stage Q (64 rows x 256d, hi+lo) with xor swizzle
#pragma unroll
    for (int i = 0; i < 16; i++) {
        int gid = i * 256 + tid;
        int mat = gid >> 11;           // 0=hi 1=lo
        int t = gid & 2047;
        int row = t >> 5, g = t & 31;
        const __nv_bfloat16* src = (mat ? qlp : qhp)
            + ((size_t)h * L_SEQ + Q0 + row) * HD + g * 8;
        uint32_t dst = sQ + mat * 32768 + row * 512 + ((g ^ (row & 7)) << 4);
        CPA16(dst, src);
    }
    CPA_COMMIT;

    float m0 = -1e9f, m1 = -1e9f;
    float l0 = 0.f, l1 = 0.f;
    float O[16][4];
#pragma unroll
    for (int nt = 0; nt < 16; nt++)
#pragma unroll
        for (int e = 0; e < 4; e++) O[nt][e] = 0.f;

    int kstart = Q0 - (WINDOW - 1);
    if (kstart < 0) kstart = 0;
    kstart &= ~(KT - 1);
    const int kend = Q0 + QB;
    const int R0 = Q0 + qg * 16;

    const int qa_r = ((lane >> 3) & 1) * 8 + (lane & 7);
    const int qa_gs = (lane >> 4);
    const int kb_r = ((lane >> 4) & 1) * 8 + (lane & 7);
    const int kb_gs = ((lane >> 3) & 1);
    const int vb_r = ((lane >> 3) & 1) * 8 + (lane & 7);
    const int vb_gs = (lane >> 4);

    CPA_WAIT0;
    __syncthreads();

    for (int kt = kstart; kt < kend; kt += KT) {
        __syncthreads();
#pragma unroll
        for (int i = 0; i < 8; i++) {
            int gid = i * 256 + tid;
            int mat = gid >> 9;
            int t = gid & 511;
            int row = t >> 5, g = t & 31;
            const __nv_bfloat16* srcb =
                (mat == 0) ? khp : (mat == 1) ? klp : (mat == 2) ? vhp : vlp;
            const __nv_bfloat16* src = srcb
                + ((size_t)kvh * L_SEQ + kt + row) * HD + g * 8;
            uint32_t dst = sKV + mat * 8192 + row * 512 + ((g ^ (row & 7)) << 4);
            CPA16(dst, src);
        }
        CPA_COMMIT;
        CPA_WAIT0;
        __syncthreads();

        float S[2][4];
#pragma unroll
        for (int nt = 0; nt < 2; nt++)
#pragma unroll
            for (int e = 0; e < 4; e++) S[nt][e] = 0.f;

#pragma unroll
        for (int ks = 0; ks < 16; ks++) {
            uint32_t qa[4], qal[4], kb[4], kbl[4];
            int qrow = qg * 16 + qa_r;
            int qg_g = ks * 2 + qa_gs;
            uint32_t qaddr = sQ + qrow * 512 + (((qg_g) ^ (qrow & 7)) << 4);
            LDM4(qa, qaddr);
            LDM4(qal, qaddr + 32768);
            int kg_g = ks * 2 + kb_gs;
            uint32_t kaddr = sKV + kb_r * 512 + (((kg_g) ^ (kb_r & 7)) << 4);
            LDM4(kb, kaddr);
            LDM4(kbl, kaddr + 8192);
            MMA16816(S[0], qa, kb[0], kb[1]);
            MMA16816(S[0], qa, kbl[0], kbl[1]);
            MMA16816(S[0], qal, kb[0], kb[1]);
            MMA16816(S[1], qa, kb[2], kb[3]);
            MMA16816(S[1], qa, kbl[2], kbl[3]);
            MMA16816(S[1], qal, kb[2], kb[3]);
        }

        const bool fullvalid = (kt + KT - 1 <= R0) && (kt >= R0 + 15 - (WINDOW - 1));
        if (!fullvalid) {
            int rq0 = R0 + (lane >> 2);
            int ck = kt + (lane & 3) * 2;
#pragma unroll
            for (int nt = 0; nt < 2; nt++)
#pragma unroll
                for (int e = 0; e < 4; e++) {
                    int q = rq0 + ((e >= 2) ? 8 : 0);
                    int k = ck + nt * 8 + (e & 1);
                    if (k > q || k < q - (WINDOW - 1)) S[nt][e] = -1e30f;
                }
        }

        float tm0 = fmaxf(fmaxf(S[0][0], S[0][1]), fmaxf(S[1][0], S[1][1]));
        float tm1 = fmaxf(fmaxf(S[0][2], S[0][3]), fmaxf(S[1][2], S[1][3]));
        tm0 = fmaxf(tm0, __shfl_xor_sync(0xffffffffu, tm0, 1));
        tm0 = fmaxf(tm0, __shfl_xor_sync(0xffffffffu, tm0, 2));
        tm1 = fmaxf(tm1, __shfl_xor_sync(0xffffffffu, tm1, 1));
        tm1 = fmaxf(tm1, __shfl_xor_sync(0xffffffffu, tm1, 2));
        float mn0 = fmaxf(m0, tm0), mn1 = fmaxf(m1, tm1);
        float sc0 = __expf(m0 - mn0), sc1 = __expf(m1 - mn1);
        m0 = mn0; m1 = mn1;

        float p[2][4];
#pragma unroll
        for (int nt = 0; nt < 2; nt++) {
            p[nt][0] = __expf(S[nt][0] - mn0);
            p[nt][1] = __expf(S[nt][1] - mn0);
            p[nt][2] = __expf(S[nt][2] - mn1);
            p[nt][3] = __expf(S[nt][3] - mn1);
        }
        float rs0 = p[0][0] + p[0][1] + p[1][0] + p[1][1];
        float rs1 = p[0][2] + p[0][3] + p[1][2] + p[1][3];
        rs0 += __shfl_xor_sync(0xffffffffu, rs0, 1);
        rs0 += __shfl_xor_sync(0xffffffffu, rs0, 2);
        rs1 += __shfl_xor_sync(0xffffffffu, rs1, 1);
        rs1 += __shfl_xor_sync(0xffffffffu, rs1, 2);
        l0 = l0 * sc0 + rs0;
        l1 = l1 * sc1 + rs1;

#pragma unroll
        for (int nt = 0; nt < 16; nt++) {
            O[nt][0] *= sc0; O[nt][1] *= sc0;
            O[nt][2] *= sc1; O[nt][3] *= sc1;
        }

        uint32_t pa[4], pal[4];
#pragma unroll
        for (int e = 0; e < 4; e++) {
            int nt = e >> 1, half = (e & 1) * 2;
            float v0 = p[nt][half], v1 = p[nt][half + 1];
            __nv_bfloat16 h0 = __float2bfloat16(v0);
            __nv_bfloat16 h1 = __float2bfloat16(v1);
            __nv_bfloat162 hh2{h0, h1};
            __nv_bfloat162 ll2{__float2bfloat16(v0 - __bfloat162float(h0)),
                               __float2bfloat16(v1 - __bfloat162float(h1))};
            pa[e] = *(uint32_t*)&hh2;
            pal[e] = *(uint32_t*)&ll2;
        }

#pragma unroll
        for (int j = 0; j < 8; j++) {
            uint32_t vb[4], vbl[4];
            int vg = dh * 16 + j * 2 + vb_gs;
            uint32_t vaddr = sKV + 16384 + vb_r * 512 + (((vg) ^ (vb_r & 7)) << 4);
            LDM4T(vb, vaddr);
            LDM4T(vbl, vaddr + 8192);
            MMA16816(O[2 * j], pa, vb[0], vb[1]);
            MMA16816(O[2 * j], pa, vbl[0], vbl[1]);
            MMA16816(O[2 * j], pal, vb[0], vb[1]);
            MMA16816(O[2 * j + 1], pa, vb[2], vb[3]);
            MMA16816(O[2 * j + 1], pa, vbl[2], vbl[3]);
            MMA16816(O[2 * j + 1], pal, vb[2], vb[3]);
        }
    }

    float il0 = 1.0f / l0, il1 = 1.0f / l1;
    int row0 = Q0 + qg * 16 + (lane >> 2);
#pragma unroll
    for (int nt = 0; nt < 16; nt++) {
        int n = dh * 128 + nt * 8 + (lane & 3) * 2;
        size_t base0 = (size_t)row0 * D_MODEL + h * HD + n;
        size_t base1 = (size_t)(row0 + 8) * D_MODEL + h * HD + n;
        float v0 = O[nt][0] * il0, v1 = O[nt][1] * il0;
        float v2 = O[nt][2] * il1, v3 = O[nt][3] * il1;
        __nv_bfloat16 h0 = __float2bfloat16(v0), h1 = __float2bfloat16(v1);
        __nv_bfloat16 h2 = __float2bfloat16(v2), h3 = __float2bfloat16(v3);
        *(__nv_bfloat162*)(oh + base0) = __nv_bfloat162{h0, h1};
        *(__nv_bfloat162*)(oh + base1) = __nv_bfloat162{h2, h3};
        *(__nv_bfloat162*)(ol + base0) =
            __nv_bfloat162{__float2bfloat16(v0 - __bfloat162float(h0)),
                           __float2bfloat16(v1 - __bfloat162float(h1))};
        *(__nv_bfloat162*)(ol + base1) =
            __nv_bfloat162{__float2bfloat16(v2 - __bfloat162float(h2)),
                           __float2bfloat16(v3 - __bfloat162float(h3))};
    }
}

// ---------------------------------------------------------------------------
extern "C" void kernel_launch(void* const* d_in, const int* in_sizes, int n_in,
                              void* d_out, int out_size) {
    const float* x       = (const float*)d_in[0];
    const int* positions = (const int*)d_in[1];
    const float* Wq      = (const float*)d_in[2];
    const float* Wk      = (const float*)d_in[3];
    const float* Wv      = (const float*)d_in[4];
    const float* Wo      = (const float*)d_in[5];
    const float* q_scale = (const float*)d_in[6];
    const float* k_scale = (const float*)d_in[7];
    float* out           = (float*)d_out;

    __nv_bfloat16 *ah, *al, *wqh, *wql, *woh, *wol, *qh, *ql, *kh, *kl, *vh, *vl;
    float* qkv;
    cudaGetSymbolAddress((void**)&ah, g_ah);
    cudaGetSymbolAddress((void**)&al, g_al);
    cudaGetSymbolAddress((void**)&wqh, g_wqkv_h);
    cudaGetSymbolAddress((void**)&wql, g_wqkv_l);
    cudaGetSymbolAddress((void**)&woh, g_wo_h);
    cudaGetSymbolAddress((void**)&wol, g_wo_l);
    cudaGetSymbolAddress((void**)&qh, g_qh);
    cudaGetSymbolAddress((void**)&ql, g_ql);
    cudaGetSymbolAddress((void**)&kh, g_kh);
    cudaGetSymbolAddress((void**)&kl, g_kl);
    cudaGetSymbolAddress((void**)&vh, g_vh);
    cudaGetSymbolAddress((void**)&vl, g_vl);
    cudaGetSymbolAddress((void**)&qkv, g_qkv);

    cudaFuncSetAttribute(gemm_hmma, cudaFuncAttributeMaxDynamicSharedMemorySize,
                         GEMM_SMEM);
    cudaFuncSetAttribute(attn_tc, cudaFuncAttributeMaxDynamicSharedMemorySize,
                         ATT_SMEM);

    // weights: transpose + bf16 split
    tsplit_kernel<<<dim3(2048 / 32, 64), dim3(32, 8)>>>(Wq, wqh, wql, 2048, 0);
    tsplit_kernel<<<dim3(512 / 32, 64), dim3(32, 8)>>>(Wk, wqh, wql, 512, 2048);
    tsplit_kernel<<<dim3(512 / 32, 64), dim3(32, 8)>>>(Wv, wqh, wql, 512, 2560);
    tsplit_kernel<<<dim3(2048 / 32, 64), dim3(32, 8)>>>(Wo, woh, wol, 2048, 0);

    // activations: bf16 split
    int n4 = (L_SEQ * D_MODEL) / 4;
    split_kernel<<<(n4 + 255) / 256, 256>>>(x, ah, al, n4);

    // fused QKV projection
    gemm_hmma<<<dim3(NQKV / 128, L_SEQ / 128), 256, GEMM_SMEM>>>(
        ah, al, wqh, wql, qkv, D_MODEL, NQKV);

    // fused norm (+rope) + split, all of q/k/v in one launch
    norm_split_all<<<dim3(L_SEQ, 12), 128>>>(qkv, q_scale, k_scale, positions,
                                             qh, ql, kh, kl, vh, vl);

    // tensor-core attention; writes split O directly into ah/al
    attn_tc<<<dim3(L_SEQ / QB, NH), 256, ATT_SMEM>>>(qh, ql, kh, kl, vh, vl, ah, al);

    // output projection: out = O @ Wo
    gemm_hmma<<<dim3(D_MODEL / 128, L_SEQ / 128), 256, GEMM_SMEM>>>(
        ah, al, woh, wol, out, D_MODEL, D_MODEL);
}